// round 1
// baseline (speedup 1.0000x reference)
#include <cuda_runtime.h>
#include <cuda_bf16.h>
#include <cstdint>

// Problem constants
#define BATCH 8
#define CCH   128
#define HH    256
#define WW    256
#define HWSZ  65536          // H*W
#define HEADS 4
#define DIMH  32
#define WS    8
#define NWIN  32             // H/WS
#define EPSLN 1e-6f

// Scratch (device globals; allocation in kernel_launch is forbidden)
__device__ float g_na[BATCH * CCH];                       // per-(b,c) scale  = norm_w*rstd
__device__ float g_nb[BATCH * CCH];                       // per-(b,c) bias   = norm_b - mean*scale
__device__ float g_qkv[(size_t)3 * CCH * BATCH * HWSZ];   // [B][3C][HW]  (805 MB)
__device__ float g_attn[(size_t)CCH * BATCH * HWSZ];      // [B][C][HW]   (268 MB)

// ---------------------------------------------------------------------------
// Kernel 1: LayerNorm2d statistics. One block per (b,c) row of 65536 floats.
// Produces affine coefficients so downstream GEMM applies xn = a*x + b.
// ---------------------------------------------------------------------------
__global__ void __launch_bounds__(256) ln_stats_kernel(
    const float* __restrict__ x,
    const float* __restrict__ norm_w,
    const float* __restrict__ norm_b,
    float* __restrict__ na, float* __restrict__ nb)
{
    const int bc = blockIdx.x;                 // b*128 + c
    const float4* xp = (const float4*)(x + (size_t)bc * HWSZ);
    float s = 0.f, q = 0.f;
    for (int i = threadIdx.x; i < HWSZ / 4; i += 256) {
        float4 v = xp[i];
        s += v.x + v.y + v.z + v.w;
        q += v.x * v.x + v.y * v.y + v.z * v.z + v.w * v.w;
    }
    __shared__ float rs[256], rq[256];
    rs[threadIdx.x] = s; rq[threadIdx.x] = q;
    __syncthreads();
    for (int st = 128; st > 0; st >>= 1) {
        if (threadIdx.x < st) {
            rs[threadIdx.x] += rs[threadIdx.x + st];
            rq[threadIdx.x] += rq[threadIdx.x + st];
        }
        __syncthreads();
    }
    if (threadIdx.x == 0) {
        const float inv_n = 1.f / (float)HWSZ;
        float mean = rs[0] * inv_n;
        float var  = rq[0] * inv_n - mean * mean;
        int c = bc & (CCH - 1);
        float a = norm_w[c] * rsqrtf(var + EPSLN);
        na[bc] = a;
        nb[bc] = norm_b[c] - mean * a;
    }
}

// ---------------------------------------------------------------------------
// Kernel 2/4: fp32 GEMM  Y[b, o, pos] = sum_c W[o,c] * Xn[b, c, pos] + bias[o]
// Tile: 64 outputs x 64 positions, K=128 in two 64-chunks.
// Optional per-(b,c) affine (fused LayerNorm) on the X tile load.
// 256 threads, 4x4 register micro-tile per thread.
// ---------------------------------------------------------------------------
__global__ void __launch_bounds__(256) gemm64_kernel(
    const float* __restrict__ X,     // [B][128][HW]
    const float* __restrict__ Wt,    // [O][128]
    const float* __restrict__ bias,  // [O]
    float* __restrict__ Y,           // [B][O][HW]
    int O, int useNorm,
    const float* __restrict__ na, const float* __restrict__ nb)
{
    __shared__ float xs[64][64];     // [k][pos]
    __shared__ float ws[64][68];     // [o][k], pad 4 (bank-safe, 16B aligned rows)

    const int b    = blockIdx.z;
    const int o0   = blockIdx.y * 64;
    const int pos0 = blockIdx.x * 64;
    const int tid  = threadIdx.x;
    const int tx   = tid & 15;       // position micro-tile index
    const int ty   = tid >> 4;       // output micro-tile index
    const int p4   = (tid & 15) * 4;
    const int r0   = tid >> 4;

    const float* Xb = X + (size_t)b * CCH * HWSZ;
    float acc[4][4] = {};

    #pragma unroll
    for (int kk = 0; kk < 128; kk += 64) {
        // Load X tile (64k x 64pos) with fused norm, and W tile (64o x 64k).
        #pragma unroll
        for (int it = 0; it < 4; it++) {
            int r = r0 + it * 16;
            int c = kk + r;
            float4 v = *(const float4*)(Xb + (size_t)c * HWSZ + pos0 + p4);
            if (useNorm) {
                float a  = na[b * CCH + c];
                float bb = nb[b * CCH + c];
                v.x = fmaf(a, v.x, bb); v.y = fmaf(a, v.y, bb);
                v.z = fmaf(a, v.z, bb); v.w = fmaf(a, v.w, bb);
            }
            *(float4*)&xs[r][p4] = v;
            float4 wv = *(const float4*)(Wt + (size_t)(o0 + r) * CCH + kk + p4);
            *(float4*)&ws[r][p4] = wv;
        }
        __syncthreads();

        #pragma unroll
        for (int k4 = 0; k4 < 16; k4++) {
            float Bv[4][4];
            #pragma unroll
            for (int oi = 0; oi < 4; oi++) {
                float4 bt = *(const float4*)&ws[ty * 4 + oi][k4 * 4];
                Bv[oi][0] = bt.x; Bv[oi][1] = bt.y; Bv[oi][2] = bt.z; Bv[oi][3] = bt.w;
            }
            #pragma unroll
            for (int j = 0; j < 4; j++) {
                float4 at = *(const float4*)&xs[k4 * 4 + j][tx * 4];
                float Av[4] = {at.x, at.y, at.z, at.w};
                #pragma unroll
                for (int oi = 0; oi < 4; oi++)
                    #pragma unroll
                    for (int pj = 0; pj < 4; pj++)
                        acc[oi][pj] = fmaf(Bv[oi][j], Av[pj], acc[oi][pj]);
            }
        }
        __syncthreads();
    }

    // Epilogue: add bias, float4 stores (coalesced).
    #pragma unroll
    for (int oi = 0; oi < 4; oi++) {
        int o = o0 + ty * 4 + oi;
        float bb = bias[o];
        float4 r;
        r.x = acc[oi][0] + bb; r.y = acc[oi][1] + bb;
        r.z = acc[oi][2] + bb; r.w = acc[oi][3] + bb;
        *(float4*)(Y + ((size_t)b * O + o) * HWSZ + pos0 + tx * 4) = r;
    }
}

// ---------------------------------------------------------------------------
// Kernel 3: window attention. One block per (b, nh, nw, head); 128 threads.
// q,k,v staged in smem as [d][t] (t = hh*8+ww), scores in [t][s].
// ---------------------------------------------------------------------------
__global__ void __launch_bounds__(128) attn_kernel(
    const float* __restrict__ qkv,   // [B][3*128][HW]
    float* __restrict__ attn_out)    // [B][128][HW]
{
    __shared__ float sq[32][68], sk[32][68], sv[32][68];
    __shared__ float sc[64][68];     // scores, later reused as out [d][t]

    const int wid  = blockIdx.x;
    const int head = wid & 3;
    const int nw_  = (wid >> 2) & 31;
    const int nh   = (wid >> 7) & 31;
    const int b    = wid >> 12;
    const int tid  = threadIdx.x;

    const size_t base = ((size_t)b * (3 * CCH) + head * DIMH) * HWSZ;
    const int sp0 = (nh * WS) * WW + nw_ * WS;

    // Load q,k,v for this window+head (2048 floats each).
    #pragma unroll
    for (int i = tid; i < 2048; i += 128) {
        int d = i >> 6, t = i & 63;
        int gpos = sp0 + (t >> 3) * WW + (t & 7);
        sq[d][t] = qkv[base + (size_t)d * HWSZ + gpos];
        sk[d][t] = qkv[base + (size_t)(CCH + d) * HWSZ + gpos];
        sv[d][t] = qkv[base + (size_t)(2 * CCH + d) * HWSZ + gpos];
    }
    __syncthreads();

    // Scores: thread computes 4 t-rows x 8 s-cols.
    {
        const int t0 = (tid >> 3) * 4;
        const int s0 = (tid & 7) * 8;
        float acc[4][8] = {};
        #pragma unroll 8
        for (int d = 0; d < 32; d++) {
            float a0 = sq[d][t0], a1 = sq[d][t0 + 1];
            float a2 = sq[d][t0 + 2], a3 = sq[d][t0 + 3];
            float4 k0 = *(const float4*)&sk[d][s0];
            float4 k1 = *(const float4*)&sk[d][s0 + 4];
            float kv[8] = {k0.x, k0.y, k0.z, k0.w, k1.x, k1.y, k1.z, k1.w};
            #pragma unroll
            for (int j = 0; j < 8; j++) {
                acc[0][j] = fmaf(a0, kv[j], acc[0][j]);
                acc[1][j] = fmaf(a1, kv[j], acc[1][j]);
                acc[2][j] = fmaf(a2, kv[j], acc[2][j]);
                acc[3][j] = fmaf(a3, kv[j], acc[3][j]);
            }
        }
        const float scale = 0.1767766952966369f;  // 32^-0.5
        #pragma unroll
        for (int i = 0; i < 4; i++)
            #pragma unroll
            for (int j = 0; j < 8; j++)
                sc[t0 + i][s0 + j] = acc[i][j] * scale;
    }
    __syncthreads();

    // Softmax per row (threads 0..63, one row each).
    if (tid < 64) {
        float m = -1e30f;
        #pragma unroll 8
        for (int s = 0; s < 64; s++) m = fmaxf(m, sc[tid][s]);
        float sum = 0.f;
        #pragma unroll 8
        for (int s = 0; s < 64; s++) {
            float e = __expf(sc[tid][s] - m);
            sc[tid][s] = e;
            sum += e;
        }
        float inv = 1.f / sum;
        #pragma unroll 8
        for (int s = 0; s < 64; s++) sc[tid][s] *= inv;
    }
    __syncthreads();

    // out[t][d] = sum_s p[t][s] * v[d][s]; thread computes 4t x 4d.
    {
        const int t0 = (tid >> 3) * 4;
        const int d0 = (tid & 7) * 4;
        float acc[4][4] = {};
        #pragma unroll 4
        for (int s4 = 0; s4 < 16; s4++) {
            float4 p[4], v[4];
            #pragma unroll
            for (int i = 0; i < 4; i++) p[i] = *(const float4*)&sc[t0 + i][s4 * 4];
            #pragma unroll
            for (int j = 0; j < 4; j++) v[j] = *(const float4*)&sv[d0 + j][s4 * 4];
            #pragma unroll
            for (int i = 0; i < 4; i++)
                #pragma unroll
                for (int j = 0; j < 4; j++) {
                    acc[i][j] = fmaf(p[i].x, v[j].x, acc[i][j]);
                    acc[i][j] = fmaf(p[i].y, v[j].y, acc[i][j]);
                    acc[i][j] = fmaf(p[i].z, v[j].z, acc[i][j]);
                    acc[i][j] = fmaf(p[i].w, v[j].w, acc[i][j]);
                }
        }
        __syncthreads();   // everyone done reading scores
        #pragma unroll
        for (int i = 0; i < 4; i++)
            #pragma unroll
            for (int j = 0; j < 4; j++)
                sc[d0 + j][t0 + i] = acc[i][j];   // reuse sc as out [d][t]
    }
    __syncthreads();

    // Coalesced writeback to [B][C][HW].
    const size_t obase = ((size_t)b * CCH + head * DIMH) * HWSZ;
    #pragma unroll
    for (int i = tid; i < 2048; i += 128) {
        int d = i >> 6, t = i & 63;
        int gpos = sp0 + (t >> 3) * WW + (t & 7);
        attn_out[obase + (size_t)d * HWSZ + gpos] = sc[d][t];
    }
}

// ---------------------------------------------------------------------------
// Launch
// ---------------------------------------------------------------------------
extern "C" void kernel_launch(void* const* d_in, const int* in_sizes, int n_in,
                              void* d_out, int out_size)
{
    const float* x      = (const float*)d_in[0];
    const float* norm_w = (const float*)d_in[1];
    const float* norm_b = (const float*)d_in[2];
    const float* qkv_w  = (const float*)d_in[3];
    const float* qkv_b  = (const float*)d_in[4];
    const float* proj_w = (const float*)d_in[5];
    const float* proj_b = (const float*)d_in[6];
    float* out = (float*)d_out;

    float *na, *nb, *qkv, *attn;
    cudaGetSymbolAddress((void**)&na,   g_na);
    cudaGetSymbolAddress((void**)&nb,   g_nb);
    cudaGetSymbolAddress((void**)&qkv,  g_qkv);
    cudaGetSymbolAddress((void**)&attn, g_attn);

    // 1) LayerNorm stats -> affine coefficients
    ln_stats_kernel<<<BATCH * CCH, 256>>>(x, norm_w, norm_b, na, nb);

    // 2) QKV GEMM with fused norm: O = 384
    gemm64_kernel<<<dim3(HWSZ / 64, 384 / 64, BATCH), 256>>>(
        x, qkv_w, qkv_b, qkv, 384, 1, na, nb);

    // 3) Window attention: 8*32*32*4 = 32768 blocks
    attn_kernel<<<BATCH * NWIN * NWIN * HEADS, 128>>>(qkv, attn);

    // 4) Projection GEMM: O = 128, writes final output
    gemm64_kernel<<<dim3(HWSZ / 64, 128 / 64, BATCH), 256>>>(
        attn, proj_w, proj_b, out, 128, 0, nullptr, nullptr);
}

// round 3
// speedup vs baseline: 1.0550x; 1.0550x over previous
#include <cuda_runtime.h>
#include <cuda_bf16.h>
#include <cstdint>

// Problem constants
#define BATCH 8
#define CCH   128
#define HH    256
#define WW    256
#define HWSZ  65536
#define HEADS 4
#define DIMH  32
#define WS    8
#define NWIN  32
#define EPSLN 1e-6f

// Scratch (device globals; allocation is forbidden)
__device__ float g_na[BATCH * CCH];
__device__ float g_nb[BATCH * CCH];
__device__ float g_qkv[(size_t)3 * CCH * BATCH * HWSZ];   // [B][3C][HW]
__device__ float g_attn[(size_t)CCH * BATCH * HWSZ];      // [B][C][HW]

// ---------------------------------------------------------------------------
// Warp-MMA helpers (base-PTX features only: legal for compute_103)
// ---------------------------------------------------------------------------
__device__ __forceinline__ uint32_t smem_u32(const void* p) {
    uint32_t a;
    asm("{ .reg .u64 t; cvta.to.shared.u64 t, %1; cvt.u32.u64 %0, t; }" : "=r"(a) : "l"(p));
    return a;
}

#define LDSM4(r, addr) \
    asm volatile("ldmatrix.sync.aligned.m8n8.x4.shared.b16 {%0,%1,%2,%3}, [%4];" \
        : "=r"((r)[0]), "=r"((r)[1]), "=r"((r)[2]), "=r"((r)[3]) : "r"(addr))

#define MMA16816(d, a, b0, b1) \
    asm volatile("mma.sync.aligned.m16n8k16.row.col.f32.bf16.bf16.f32 " \
        "{%0,%1,%2,%3}, {%4,%5,%6,%7}, {%8,%9}, {%0,%1,%2,%3};" \
        : "+f"((d)[0]), "+f"((d)[1]), "+f"((d)[2]), "+f"((d)[3]) \
        : "r"((a)[0]), "r"((a)[1]), "r"((a)[2]), "r"((a)[3]), "r"(b0), "r"(b1))

// ---------------------------------------------------------------------------
// Kernel 1: LayerNorm2d stats -> per-(b,c) affine coefficients
// ---------------------------------------------------------------------------
__global__ void __launch_bounds__(256) ln_stats_kernel(
    const float* __restrict__ x,
    const float* __restrict__ norm_w,
    const float* __restrict__ norm_b,
    float* __restrict__ na, float* __restrict__ nb)
{
    const int bc = blockIdx.x;
    const float4* xp = (const float4*)(x + (size_t)bc * HWSZ);
    float s = 0.f, q = 0.f;
    for (int i = threadIdx.x; i < HWSZ / 4; i += 256) {
        float4 v = xp[i];
        s += v.x + v.y + v.z + v.w;
        q += v.x * v.x + v.y * v.y + v.z * v.z + v.w * v.w;
    }
    __shared__ float rs[256], rq[256];
    rs[threadIdx.x] = s; rq[threadIdx.x] = q;
    __syncthreads();
    for (int st = 128; st > 0; st >>= 1) {
        if (threadIdx.x < st) {
            rs[threadIdx.x] += rs[threadIdx.x + st];
            rq[threadIdx.x] += rq[threadIdx.x + st];
        }
        __syncthreads();
    }
    if (threadIdx.x == 0) {
        const float inv_n = 1.f / (float)HWSZ;
        float mean = rs[0] * inv_n;
        float var  = rq[0] * inv_n - mean * mean;
        int c = bc & (CCH - 1);
        float a = norm_w[c] * rsqrtf(var + EPSLN);
        na[bc] = a;
        nb[bc] = norm_b[c] - mean * a;
    }
}

// ---------------------------------------------------------------------------
// mma.sync GEMM: Y[b, o, pos] = sum_c W[o,c] * Xn[b,c,pos] + bias[o]
// CTA tile: NT*128 outputs x 128 positions, K=128, bf16 split (3 terms).
// smem: Wh/Wl/Xh/Xl bf16 tiles [128][pitch 136], fp32 staging [128][132].
// ---------------------------------------------------------------------------
#define APITCH 136
#define SPITCH 132
#define SM_WH  0u
#define SM_WL  34816u
#define SM_XH  69632u
#define SM_XL  104448u
#define SM_STG 139264u
#define SM_TOTAL (139264u + 128u * SPITCH * 4u)   // 206848

__device__ __forceinline__ void split_pack(float f0, float f1, uint32_t& hi, uint32_t& lo) {
    __nv_bfloat16 h0 = __float2bfloat16(f0);
    __nv_bfloat16 h1 = __float2bfloat16(f1);
    __nv_bfloat16 l0 = __float2bfloat16(f0 - __bfloat162float(h0));
    __nv_bfloat16 l1 = __float2bfloat16(f1 - __bfloat162float(h1));
    hi = (uint32_t)__bfloat16_as_ushort(h0) | ((uint32_t)__bfloat16_as_ushort(h1) << 16);
    lo = (uint32_t)__bfloat16_as_ushort(l0) | ((uint32_t)__bfloat16_as_ushort(l1) << 16);
}

template<int NT, bool NORM>
__global__ void __launch_bounds__(256, 1) mma_gemm_kernel(
    const float* __restrict__ X,     // [B][128][HW]
    const float* __restrict__ Wt,    // [NT*128][128]
    const float* __restrict__ bias,  // [NT*128]
    float* __restrict__ Y,           // [B][NT*128][HW]
    const float* __restrict__ na, const float* __restrict__ nb)
{
    extern __shared__ char smem[];
    const uint32_t sb = smem_u32(smem);
    float* stg = (float*)(smem + SM_STG);

    const int tid  = threadIdx.x;
    const int wid  = tid >> 5;
    const int lane = tid & 31;
    const int wm   = wid & 3;        // M group (o)
    const int wn   = wid >> 2;       // N group (pos)
    const int b    = blockIdx.y;
    const int pos0 = blockIdx.x * 128;

    // --- Stage X tile [c][pos] fp32, coalesced, LN affine fused ---
    const float* Xb = X + (size_t)b * CCH * HWSZ;
    for (int i = tid; i < 128 * 32; i += 256) {
        int c = i >> 5, p4 = (i & 31) * 4;
        float4 v = *(const float4*)(Xb + (size_t)c * HWSZ + pos0 + p4);
        if (NORM) {
            float a = na[b * CCH + c], bb = nb[b * CCH + c];
            v.x = fmaf(a, v.x, bb); v.y = fmaf(a, v.y, bb);
            v.z = fmaf(a, v.z, bb); v.w = fmaf(a, v.w, bb);
        }
        *(float4*)&stg[c * SPITCH + p4] = v;
    }
    __syncthreads();

    // --- Transpose + split into Xh/Xl [pos][c] bf16 (pitch 136) ---
    for (int j = tid; j < 128 * 32; j += 256) {
        int pos = j & 127, c4 = (j >> 7) << 2;
        uint32_t h0, l0, h1, l1;
        split_pack(stg[(c4 + 0) * SPITCH + pos], stg[(c4 + 1) * SPITCH + pos], h0, l0);
        split_pack(stg[(c4 + 2) * SPITCH + pos], stg[(c4 + 3) * SPITCH + pos], h1, l1);
        uint32_t off = (uint32_t)(pos * APITCH + c4) * 2u;
        *(uint2*)(smem + SM_XH + off) = make_uint2(h0, h1);
        *(uint2*)(smem + SM_XL + off) = make_uint2(l0, l1);
    }

    for (int ot = 0; ot < NT; ot++) {
        // --- Split-convert W tile [o][c] -> Wh/Wl ---
        const float* Wp = Wt + (size_t)ot * 128 * CCH;
        for (int j = tid; j < 128 * 32; j += 256) {
            int o = j >> 5, c4 = (j & 31) << 2;
            float4 v = *(const float4*)(Wp + o * CCH + c4);
            uint32_t h0, l0, h1, l1;
            split_pack(v.x, v.y, h0, l0);
            split_pack(v.z, v.w, h1, l1);
            uint32_t off = (uint32_t)(o * APITCH + c4) * 2u;
            *(uint2*)(smem + SM_WH + off) = make_uint2(h0, h1);
            *(uint2*)(smem + SM_WL + off) = make_uint2(l0, l1);
        }
        __syncthreads();

        // --- Mainloop: 3 split terms x 8 k-steps x (2 M x 8 N) mma ---
        float acc[2][8][4];
        #pragma unroll
        for (int mi = 0; mi < 2; mi++)
            #pragma unroll
            for (int nf = 0; nf < 8; nf++)
                #pragma unroll
                for (int e = 0; e < 4; e++) acc[mi][nf][e] = 0.f;

        #pragma unroll
        for (int term = 0; term < 3; term++) {
            const uint32_t sA = sb + ((term == 2) ? SM_WL : SM_WH);
            const uint32_t sB = sb + ((term == 1) ? SM_XL : SM_XH);
            // ldmatrix lane addresses (A: m16k16 frags; B: n16k16 frags)
            const uint32_t aaddr = sA +
                (uint32_t)((wm * 32 + (lane & 15)) * APITCH + (lane >> 4) * 8) * 2u;
            const uint32_t baddr = sB +
                (uint32_t)((wn * 64 + (lane & 7) + ((lane >> 4) & 1) * 8) * APITCH
                           + ((lane >> 3) & 1) * 8) * 2u;
            #pragma unroll
            for (int ks = 0; ks < 8; ks++) {
                uint32_t a0[4], a1[4], bb[4][4];
                LDSM4(a0, aaddr + ks * 32);
                LDSM4(a1, aaddr + 16 * APITCH * 2 + ks * 32);
                #pragma unroll
                for (int j = 0; j < 4; j++)
                    LDSM4(bb[j], baddr + j * 16 * APITCH * 2 + ks * 32);
                #pragma unroll
                for (int j = 0; j < 4; j++) {
                    MMA16816(acc[0][2 * j],     a0, bb[j][0], bb[j][1]);
                    MMA16816(acc[0][2 * j + 1], a0, bb[j][2], bb[j][3]);
                    MMA16816(acc[1][2 * j],     a1, bb[j][0], bb[j][1]);
                    MMA16816(acc[1][2 * j + 1], a1, bb[j][2], bb[j][3]);
                }
            }
        }
        __syncthreads();   // all warps done reading tiles; staging reusable

        // --- Epilogue: frags -> fp32 staging (pitch 132) ---
        #pragma unroll
        for (int mi = 0; mi < 2; mi++)
            #pragma unroll
            for (int nf = 0; nf < 8; nf++) {
                int r  = wm * 32 + mi * 16 + (lane >> 2);
                int cc = wn * 64 + nf * 8 + (lane & 3) * 2;
                *(float2*)&stg[r * SPITCH + cc] =
                    make_float2(acc[mi][nf][0], acc[mi][nf][1]);
                *(float2*)&stg[(r + 8) * SPITCH + cc] =
                    make_float2(acc[mi][nf][2], acc[mi][nf][3]);
            }
        __syncthreads();

        // --- Coalesced store with bias ---
        for (int i = tid; i < 128 * 32; i += 256) {
            int r = i >> 5, c4 = (i & 31) * 4;
            int orow = ot * 128 + r;
            float bv = bias[orow];
            float4 v = *(float4*)&stg[r * SPITCH + c4];
            v.x += bv; v.y += bv; v.z += bv; v.w += bv;
            *(float4*)(Y + ((size_t)b * (NT * 128) + orow) * HWSZ + pos0 + c4) = v;
        }
        __syncthreads();   // before overwriting W tiles / staging next ot
    }
}

// ---------------------------------------------------------------------------
// Kernel 3: window attention (unchanged, known-good SIMT fp32)
// ---------------------------------------------------------------------------
__global__ void __launch_bounds__(128) attn_kernel(
    const float* __restrict__ qkv,
    float* __restrict__ attn_out)
{
    __shared__ float sq[32][68], sk[32][68], sv[32][68];
    __shared__ float sc[64][68];

    const int wid  = blockIdx.x;
    const int head = wid & 3;
    const int nw_  = (wid >> 2) & 31;
    const int nh   = (wid >> 7) & 31;
    const int b    = wid >> 12;
    const int tid  = threadIdx.x;

    const size_t base = ((size_t)b * (3 * CCH) + head * DIMH) * HWSZ;
    const int sp0 = (nh * WS) * WW + nw_ * WS;

    #pragma unroll
    for (int i = tid; i < 2048; i += 128) {
        int d = i >> 6, t = i & 63;
        int gpos = sp0 + (t >> 3) * WW + (t & 7);
        sq[d][t] = qkv[base + (size_t)d * HWSZ + gpos];
        sk[d][t] = qkv[base + (size_t)(CCH + d) * HWSZ + gpos];
        sv[d][t] = qkv[base + (size_t)(2 * CCH + d) * HWSZ + gpos];
    }
    __syncthreads();

    {
        const int t0 = (tid >> 3) * 4;
        const int s0 = (tid & 7) * 8;
        float acc[4][8] = {};
        #pragma unroll 8
        for (int d = 0; d < 32; d++) {
            float a0 = sq[d][t0], a1 = sq[d][t0 + 1];
            float a2 = sq[d][t0 + 2], a3 = sq[d][t0 + 3];
            float4 k0 = *(const float4*)&sk[d][s0];
            float4 k1 = *(const float4*)&sk[d][s0 + 4];
            float kv[8] = {k0.x, k0.y, k0.z, k0.w, k1.x, k1.y, k1.z, k1.w};
            #pragma unroll
            for (int j = 0; j < 8; j++) {
                acc[0][j] = fmaf(a0, kv[j], acc[0][j]);
                acc[1][j] = fmaf(a1, kv[j], acc[1][j]);
                acc[2][j] = fmaf(a2, kv[j], acc[2][j]);
                acc[3][j] = fmaf(a3, kv[j], acc[3][j]);
            }
        }
        const float scale = 0.1767766952966369f;
        #pragma unroll
        for (int i = 0; i < 4; i++)
            #pragma unroll
            for (int j = 0; j < 8; j++)
                sc[t0 + i][s0 + j] = acc[i][j] * scale;
    }
    __syncthreads();

    if (tid < 64) {
        float m = -1e30f;
        #pragma unroll 8
        for (int s = 0; s < 64; s++) m = fmaxf(m, sc[tid][s]);
        float sum = 0.f;
        #pragma unroll 8
        for (int s = 0; s < 64; s++) {
            float e = __expf(sc[tid][s] - m);
            sc[tid][s] = e;
            sum += e;
        }
        float inv = 1.f / sum;
        #pragma unroll 8
        for (int s = 0; s < 64; s++) sc[tid][s] *= inv;
    }
    __syncthreads();

    {
        const int t0 = (tid >> 3) * 4;
        const int d0 = (tid & 7) * 4;
        float acc[4][4] = {};
        #pragma unroll 4
        for (int s4 = 0; s4 < 16; s4++) {
            float4 p[4], v[4];
            #pragma unroll
            for (int i = 0; i < 4; i++) p[i] = *(const float4*)&sc[t0 + i][s4 * 4];
            #pragma unroll
            for (int j = 0; j < 4; j++) v[j] = *(const float4*)&sv[d0 + j][s4 * 4];
            #pragma unroll
            for (int i = 0; i < 4; i++)
                #pragma unroll
                for (int j = 0; j < 4; j++) {
                    acc[i][j] = fmaf(p[i].x, v[j].x, acc[i][j]);
                    acc[i][j] = fmaf(p[i].y, v[j].y, acc[i][j]);
                    acc[i][j] = fmaf(p[i].z, v[j].z, acc[i][j]);
                    acc[i][j] = fmaf(p[i].w, v[j].w, acc[i][j]);
                }
        }
        __syncthreads();
        #pragma unroll
        for (int i = 0; i < 4; i++)
            #pragma unroll
            for (int j = 0; j < 4; j++)
                sc[d0 + j][t0 + i] = acc[i][j];
    }
    __syncthreads();

    const size_t obase = ((size_t)b * CCH + head * DIMH) * HWSZ;
    #pragma unroll
    for (int i = tid; i < 2048; i += 128) {
        int d = i >> 6, t = i & 63;
        int gpos = sp0 + (t >> 3) * WW + (t & 7);
        attn_out[obase + (size_t)d * HWSZ + gpos] = sc[d][t];
    }
}

// ---------------------------------------------------------------------------
// Launch
// ---------------------------------------------------------------------------
extern "C" void kernel_launch(void* const* d_in, const int* in_sizes, int n_in,
                              void* d_out, int out_size)
{
    const float* x      = (const float*)d_in[0];
    const float* norm_w = (const float*)d_in[1];
    const float* norm_b = (const float*)d_in[2];
    const float* qkv_w  = (const float*)d_in[3];
    const float* qkv_b  = (const float*)d_in[4];
    const float* proj_w = (const float*)d_in[5];
    const float* proj_b = (const float*)d_in[6];
    float* out = (float*)d_out;

    float *na, *nb, *qkv, *attn;
    cudaGetSymbolAddress((void**)&na,   g_na);
    cudaGetSymbolAddress((void**)&nb,   g_nb);
    cudaGetSymbolAddress((void**)&qkv,  g_qkv);
    cudaGetSymbolAddress((void**)&attn, g_attn);

    cudaFuncSetAttribute(mma_gemm_kernel<3, true>,
                         cudaFuncAttributeMaxDynamicSharedMemorySize, SM_TOTAL);
    cudaFuncSetAttribute(mma_gemm_kernel<1, false>,
                         cudaFuncAttributeMaxDynamicSharedMemorySize, SM_TOTAL);

    // 1) LayerNorm stats
    ln_stats_kernel<<<BATCH * CCH, 256>>>(x, norm_w, norm_b, na, nb);

    // 2) QKV GEMM (HMMA, fused norm)
    mma_gemm_kernel<3, true><<<dim3(HWSZ / 128, BATCH), 256, SM_TOTAL>>>(
        x, qkv_w, qkv_b, qkv, na, nb);

    // 3) Window attention
    attn_kernel<<<BATCH * NWIN * NWIN * HEADS, 128>>>(qkv, attn);

    // 4) Projection GEMM (HMMA)
    mma_gemm_kernel<1, false><<<dim3(HWSZ / 128, BATCH), 256, SM_TOTAL>>>(
        attn, proj_w, proj_b, out, nullptr, nullptr);
}

// round 4
// speedup vs baseline: 1.3844x; 1.3123x over previous
#include <cuda_runtime.h>
#include <cuda_bf16.h>
#include <cstdint>

// Problem constants
#define BATCH 8
#define CCH   128
#define HH    256
#define WW    256
#define HWSZ  65536
#define HEADS 4
#define DIMH  32
#define WS    8
#define NWIN  32
#define EPSLN 1e-6f

// Scratch (device globals; allocation is forbidden)
__device__ float g_na[BATCH * CCH];
__device__ float g_nb[BATCH * CCH];
__device__ float g_qkv[(size_t)3 * CCH * BATCH * HWSZ];   // [B][3C][HW]
__device__ float g_attn[(size_t)CCH * BATCH * HWSZ];      // [B][C][HW]
__device__ __nv_bfloat16 g_wh[(3 + 1) * CCH * CCH];       // qkv_w then proj_w, hi
__device__ __nv_bfloat16 g_wl[(3 + 1) * CCH * CCH];       // lo

// ---------------------------------------------------------------------------
// Warp-MMA helpers (base-PTX features only: legal for compute_103)
// ---------------------------------------------------------------------------
__device__ __forceinline__ uint32_t smem_u32(const void* p) {
    uint32_t a;
    asm("{ .reg .u64 t; cvta.to.shared.u64 t, %1; cvt.u32.u64 %0, t; }" : "=r"(a) : "l"(p));
    return a;
}

#define LDSM4(r, addr) \
    asm volatile("ldmatrix.sync.aligned.m8n8.x4.shared.b16 {%0,%1,%2,%3}, [%4];" \
        : "=r"((r)[0]), "=r"((r)[1]), "=r"((r)[2]), "=r"((r)[3]) : "r"(addr))

#define LDSM4T(r, addr) \
    asm volatile("ldmatrix.sync.aligned.m8n8.x4.trans.shared.b16 {%0,%1,%2,%3}, [%4];" \
        : "=r"((r)[0]), "=r"((r)[1]), "=r"((r)[2]), "=r"((r)[3]) : "r"(addr))

#define MMA16816(d, a, b0, b1) \
    asm volatile("mma.sync.aligned.m16n8k16.row.col.f32.bf16.bf16.f32 " \
        "{%0,%1,%2,%3}, {%4,%5,%6,%7}, {%8,%9}, {%0,%1,%2,%3};" \
        : "+f"((d)[0]), "+f"((d)[1]), "+f"((d)[2]), "+f"((d)[3]) \
        : "r"((a)[0]), "r"((a)[1]), "r"((a)[2]), "r"((a)[3]), "r"(b0), "r"(b1))

__device__ __forceinline__ void split_pack(float f0, float f1, uint32_t& hi, uint32_t& lo) {
    __nv_bfloat16 h0 = __float2bfloat16(f0);
    __nv_bfloat16 h1 = __float2bfloat16(f1);
    __nv_bfloat16 l0 = __float2bfloat16(f0 - __bfloat162float(h0));
    __nv_bfloat16 l1 = __float2bfloat16(f1 - __bfloat162float(h1));
    hi = (uint32_t)__bfloat16_as_ushort(h0) | ((uint32_t)__bfloat16_as_ushort(h1) << 16);
    lo = (uint32_t)__bfloat16_as_ushort(l0) | ((uint32_t)__bfloat16_as_ushort(l1) << 16);
}

// ---------------------------------------------------------------------------
// Kernel 0: split weights into bf16 hi/lo (runs once per launch, tiny)
// ---------------------------------------------------------------------------
__global__ void wsplit_kernel(const float* __restrict__ qkv_w,
                              const float* __restrict__ proj_w,
                              __nv_bfloat16* __restrict__ wh,
                              __nv_bfloat16* __restrict__ wl)
{
    int i = blockIdx.x * 256 + threadIdx.x;
    const int nq = 3 * CCH * CCH;
    const int nt = 4 * CCH * CCH;
    if (i < nt) {
        float f = (i < nq) ? qkv_w[i] : proj_w[i - nq];
        __nv_bfloat16 h = __float2bfloat16(f);
        wh[i] = h;
        wl[i] = __float2bfloat16(f - __bfloat162float(h));
    }
}

// ---------------------------------------------------------------------------
// Kernel 1: LayerNorm2d stats -> per-(b,c) affine coefficients
// ---------------------------------------------------------------------------
__global__ void __launch_bounds__(256) ln_stats_kernel(
    const float* __restrict__ x,
    const float* __restrict__ norm_w,
    const float* __restrict__ norm_b,
    float* __restrict__ na, float* __restrict__ nb)
{
    const int bc = blockIdx.x;
    const float4* xp = (const float4*)(x + (size_t)bc * HWSZ);
    float s = 0.f, q = 0.f;
    for (int i = threadIdx.x; i < HWSZ / 4; i += 256) {
        float4 v = xp[i];
        s += v.x + v.y + v.z + v.w;
        q += v.x * v.x + v.y * v.y + v.z * v.z + v.w * v.w;
    }
    __shared__ float rs[256], rq[256];
    rs[threadIdx.x] = s; rq[threadIdx.x] = q;
    __syncthreads();
    for (int st = 128; st > 0; st >>= 1) {
        if (threadIdx.x < st) {
            rs[threadIdx.x] += rs[threadIdx.x + st];
            rq[threadIdx.x] += rq[threadIdx.x + st];
        }
        __syncthreads();
    }
    if (threadIdx.x == 0) {
        const float inv_n = 1.f / (float)HWSZ;
        float mean = rs[0] * inv_n;
        float var  = rq[0] * inv_n - mean * mean;
        int c = bc & (CCH - 1);
        float a = norm_w[c] * rsqrtf(var + EPSLN);
        na[bc] = a;
        nb[bc] = norm_b[c] - mean * a;
    }
}

// ---------------------------------------------------------------------------
// mma.sync GEMM v2: Y[b,o,pos] = sum_c W[o,c]*Xn[b,c,pos] + bias[o]
// CTA: NT*128 o x 64 pos, K=128. 8 warps: wm=wid&3 (32 o), wn=wid>>2 (32 pos).
// X stored [c][pos] bf16 (no transpose); B frags via ldmatrix.trans.
// smem 104KB -> 2 CTAs/SM.
// ---------------------------------------------------------------------------
#define WP 136   // W pitch (bf16 elems)
#define XP 72    // X pitch
#define SM_WH 0u
#define SM_WL 34816u
#define SM_XH 69632u
#define SM_XL 88064u
#define SM_TOTAL 106496u

template<int NT, bool NORM>
__global__ void __launch_bounds__(256, 2) gemm_v2_kernel(
    const float* __restrict__ X,          // [B][128][HW]
    const __nv_bfloat16* __restrict__ Wh, // [NT*128][128]
    const __nv_bfloat16* __restrict__ Wl,
    const float* __restrict__ bias,       // [NT*128]
    float* __restrict__ Y,                // [B][NT*128][HW]
    const float* __restrict__ na, const float* __restrict__ nb)
{
    extern __shared__ char smem[];
    const uint32_t sb = smem_u32(smem);
    const int tid  = threadIdx.x;
    const int wid  = tid >> 5;
    const int lane = tid & 31;
    const int wm   = wid & 3;
    const int wn   = wid >> 2;
    const int b    = blockIdx.y;
    const int pos0 = blockIdx.x * 64;

    // --- X load + split: [c][pos] bf16, LN affine fused, no transpose ---
    const float* Xb = X + (size_t)b * CCH * HWSZ + pos0;
    for (int i = tid; i < 128 * 16; i += 256) {
        int c = i >> 4, p4 = (i & 15) * 4;
        float4 v = *(const float4*)(Xb + (size_t)c * HWSZ + p4);
        if (NORM) {
            float a = na[b * CCH + c], bb = nb[b * CCH + c];
            v.x = fmaf(a, v.x, bb); v.y = fmaf(a, v.y, bb);
            v.z = fmaf(a, v.z, bb); v.w = fmaf(a, v.w, bb);
        }
        uint32_t h0, l0, h1, l1;
        split_pack(v.x, v.y, h0, l0);
        split_pack(v.z, v.w, h1, l1);
        uint32_t off = (uint32_t)(c * XP + p4) * 2u;
        *(uint2*)(smem + SM_XH + off) = make_uint2(h0, h1);
        *(uint2*)(smem + SM_XL + off) = make_uint2(l0, l1);
    }

    for (int ot = 0; ot < NT; ot++) {
        // --- W tiles: straight bf16 copies (precomputed hi/lo, L2-hot) ---
        const __nv_bfloat16* WhT = Wh + (size_t)ot * 128 * CCH;
        const __nv_bfloat16* WlT = Wl + (size_t)ot * 128 * CCH;
        for (int i = tid; i < 128 * 16; i += 256) {
            int o = i >> 4, c8 = (i & 15) * 8;
            uint32_t off = (uint32_t)(o * WP + c8) * 2u;
            *(uint4*)(smem + SM_WH + off) = *(const uint4*)(WhT + o * CCH + c8);
            *(uint4*)(smem + SM_WL + off) = *(const uint4*)(WlT + o * CCH + c8);
        }
        __syncthreads();

        // --- Mainloop: 3 split terms x 8 k-steps ---
        float acc[2][4][4];
        #pragma unroll
        for (int mi = 0; mi < 2; mi++)
            #pragma unroll
            for (int nf = 0; nf < 4; nf++)
                #pragma unroll
                for (int e = 0; e < 4; e++) acc[mi][nf][e] = 0.f;

        #pragma unroll 1
        for (int term = 0; term < 3; term++) {
            const uint32_t sA = sb + ((term == 2) ? SM_WL : SM_WH);
            const uint32_t sB = sb + ((term == 1) ? SM_XL : SM_XH);
            const uint32_t aaddr = sA +
                (uint32_t)((wm * 32 + (lane & 15)) * WP + (lane >> 4) * 8) * 2u;
            const uint32_t baddr = sB +
                (uint32_t)((lane & 15) * XP + wn * 32 + ((lane >> 4) & 1) * 8) * 2u;
            #pragma unroll
            for (int ks = 0; ks < 8; ks++) {
                uint32_t a0[4], a1[4], b0[4], b1[4];
                LDSM4 (a0, aaddr + ks * 32);
                LDSM4 (a1, aaddr + 16 * WP * 2 + ks * 32);
                LDSM4T(b0, baddr + ks * 16 * XP * 2);
                LDSM4T(b1, baddr + ks * 16 * XP * 2 + 32);
                MMA16816(acc[0][0], a0, b0[0], b0[1]);
                MMA16816(acc[0][1], a0, b0[2], b0[3]);
                MMA16816(acc[0][2], a0, b1[0], b1[1]);
                MMA16816(acc[0][3], a0, b1[2], b1[3]);
                MMA16816(acc[1][0], a1, b0[0], b0[1]);
                MMA16816(acc[1][1], a1, b0[2], b0[3]);
                MMA16816(acc[1][2], a1, b1[0], b1[1]);
                MMA16816(acc[1][3], a1, b1[2], b1[3]);
            }
        }
        __syncthreads();   // all MMA reads done before next ot overwrites W

        // --- Epilogue: direct float2 stores (full 32B sectors) + bias ---
        #pragma unroll
        for (int mi = 0; mi < 2; mi++) {
            int r = ot * 128 + wm * 32 + mi * 16 + (lane >> 2);
            float bv0 = bias[r], bv1 = bias[r + 8];
            float* Y0 = Y + ((size_t)b * (NT * 128) + r) * HWSZ
                          + pos0 + wn * 32 + (lane & 3) * 2;
            #pragma unroll
            for (int nf = 0; nf < 4; nf++) {
                *(float2*)(Y0 + nf * 8) =
                    make_float2(acc[mi][nf][0] + bv0, acc[mi][nf][1] + bv0);
                *(float2*)(Y0 + (size_t)8 * HWSZ + nf * 8) =
                    make_float2(acc[mi][nf][2] + bv1, acc[mi][nf][3] + bv1);
            }
        }
    }
}

// ---------------------------------------------------------------------------
// Kernel 3: window attention (unchanged, known-good SIMT fp32)
// ---------------------------------------------------------------------------
__global__ void __launch_bounds__(128) attn_kernel(
    const float* __restrict__ qkv,
    float* __restrict__ attn_out)
{
    __shared__ float sq[32][68], sk[32][68], sv[32][68];
    __shared__ float sc[64][68];

    const int wid  = blockIdx.x;
    const int head = wid & 3;
    const int nw_  = (wid >> 2) & 31;
    const int nh   = (wid >> 7) & 31;
    const int b    = wid >> 12;
    const int tid  = threadIdx.x;

    const size_t base = ((size_t)b * (3 * CCH) + head * DIMH) * HWSZ;
    const int sp0 = (nh * WS) * WW + nw_ * WS;

    #pragma unroll
    for (int i = tid; i < 2048; i += 128) {
        int d = i >> 6, t = i & 63;
        int gpos = sp0 + (t >> 3) * WW + (t & 7);
        sq[d][t] = qkv[base + (size_t)d * HWSZ + gpos];
        sk[d][t] = qkv[base + (size_t)(CCH + d) * HWSZ + gpos];
        sv[d][t] = qkv[base + (size_t)(2 * CCH + d) * HWSZ + gpos];
    }
    __syncthreads();

    {
        const int t0 = (tid >> 3) * 4;
        const int s0 = (tid & 7) * 8;
        float acc[4][8] = {};
        #pragma unroll 8
        for (int d = 0; d < 32; d++) {
            float a0 = sq[d][t0], a1 = sq[d][t0 + 1];
            float a2 = sq[d][t0 + 2], a3 = sq[d][t0 + 3];
            float4 k0 = *(const float4*)&sk[d][s0];
            float4 k1 = *(const float4*)&sk[d][s0 + 4];
            float kv[8] = {k0.x, k0.y, k0.z, k0.w, k1.x, k1.y, k1.z, k1.w};
            #pragma unroll
            for (int j = 0; j < 8; j++) {
                acc[0][j] = fmaf(a0, kv[j], acc[0][j]);
                acc[1][j] = fmaf(a1, kv[j], acc[1][j]);
                acc[2][j] = fmaf(a2, kv[j], acc[2][j]);
                acc[3][j] = fmaf(a3, kv[j], acc[3][j]);
            }
        }
        const float scale = 0.1767766952966369f;
        #pragma unroll
        for (int i = 0; i < 4; i++)
            #pragma unroll
            for (int j = 0; j < 8; j++)
                sc[t0 + i][s0 + j] = acc[i][j] * scale;
    }
    __syncthreads();

    if (tid < 64) {
        float m = -1e30f;
        #pragma unroll 8
        for (int s = 0; s < 64; s++) m = fmaxf(m, sc[tid][s]);
        float sum = 0.f;
        #pragma unroll 8
        for (int s = 0; s < 64; s++) {
            float e = __expf(sc[tid][s] - m);
            sc[tid][s] = e;
            sum += e;
        }
        float inv = 1.f / sum;
        #pragma unroll 8
        for (int s = 0; s < 64; s++) sc[tid][s] *= inv;
    }
    __syncthreads();

    {
        const int t0 = (tid >> 3) * 4;
        const int d0 = (tid & 7) * 4;
        float acc[4][4] = {};
        #pragma unroll 4
        for (int s4 = 0; s4 < 16; s4++) {
            float4 p[4], v[4];
            #pragma unroll
            for (int i = 0; i < 4; i++) p[i] = *(const float4*)&sc[t0 + i][s4 * 4];
            #pragma unroll
            for (int j = 0; j < 4; j++) v[j] = *(const float4*)&sv[d0 + j][s4 * 4];
            #pragma unroll
            for (int i = 0; i < 4; i++)
                #pragma unroll
                for (int j = 0; j < 4; j++) {
                    acc[i][j] = fmaf(p[i].x, v[j].x, acc[i][j]);
                    acc[i][j] = fmaf(p[i].y, v[j].y, acc[i][j]);
                    acc[i][j] = fmaf(p[i].z, v[j].z, acc[i][j]);
                    acc[i][j] = fmaf(p[i].w, v[j].w, acc[i][j]);
                }
        }
        __syncthreads();
        #pragma unroll
        for (int i = 0; i < 4; i++)
            #pragma unroll
            for (int j = 0; j < 4; j++)
                sc[d0 + j][t0 + i] = acc[i][j];
    }
    __syncthreads();

    const size_t obase = ((size_t)b * CCH + head * DIMH) * HWSZ;
    #pragma unroll
    for (int i = tid; i < 2048; i += 128) {
        int d = i >> 6, t = i & 63;
        int gpos = sp0 + (t >> 3) * WW + (t & 7);
        attn_out[obase + (size_t)d * HWSZ + gpos] = sc[d][t];
    }
}

// ---------------------------------------------------------------------------
// Launch
// ---------------------------------------------------------------------------
extern "C" void kernel_launch(void* const* d_in, const int* in_sizes, int n_in,
                              void* d_out, int out_size)
{
    const float* x      = (const float*)d_in[0];
    const float* norm_w = (const float*)d_in[1];
    const float* norm_b = (const float*)d_in[2];
    const float* qkv_w  = (const float*)d_in[3];
    const float* qkv_b  = (const float*)d_in[4];
    const float* proj_w = (const float*)d_in[5];
    const float* proj_b = (const float*)d_in[6];
    float* out = (float*)d_out;

    float *na, *nb, *qkv, *attn;
    __nv_bfloat16 *wh, *wl;
    cudaGetSymbolAddress((void**)&na,   g_na);
    cudaGetSymbolAddress((void**)&nb,   g_nb);
    cudaGetSymbolAddress((void**)&qkv,  g_qkv);
    cudaGetSymbolAddress((void**)&attn, g_attn);
    cudaGetSymbolAddress((void**)&wh,   g_wh);
    cudaGetSymbolAddress((void**)&wl,   g_wl);

    cudaFuncSetAttribute(gemm_v2_kernel<3, true>,
                         cudaFuncAttributeMaxDynamicSharedMemorySize, SM_TOTAL);
    cudaFuncSetAttribute(gemm_v2_kernel<1, false>,
                         cudaFuncAttributeMaxDynamicSharedMemorySize, SM_TOTAL);

    // 0) Weight split (tiny)
    wsplit_kernel<<<(4 * CCH * CCH + 255) / 256, 256>>>(qkv_w, proj_w, wh, wl);

    // 1) LayerNorm stats
    ln_stats_kernel<<<BATCH * CCH, 256>>>(x, norm_w, norm_b, na, nb);

    // 2) QKV GEMM (HMMA, fused norm)
    gemm_v2_kernel<3, true><<<dim3(HWSZ / 64, BATCH), 256, SM_TOTAL>>>(
        x, wh, wl, qkv_b, qkv, na, nb);

    // 3) Window attention
    attn_kernel<<<BATCH * NWIN * NWIN * HEADS, 128>>>(qkv, attn);

    // 4) Projection GEMM (HMMA)
    gemm_v2_kernel<1, false><<<dim3(HWSZ / 64, BATCH), 256, SM_TOTAL>>>(
        attn, wh + 3 * CCH * CCH, wl + 3 * CCH * CCH, proj_b, out, nullptr, nullptr);
}

// round 5
// speedup vs baseline: 2.0806x; 1.5029x over previous
#include <cuda_runtime.h>
#include <cuda_bf16.h>
#include <cstdint>

// Problem constants
#define BATCH 8
#define CCH   128
#define HH    256
#define WW    256
#define HWSZ  65536
#define HEADS 4
#define DIMH  32
#define WS    8
#define NWIN  32
#define EPSLN 1e-6f

// Scratch (device globals; allocation is forbidden)
__device__ float g_na[BATCH * CCH];
__device__ float g_nb[BATCH * CCH];
__device__ float g_qkv[(size_t)3 * CCH * BATCH * HWSZ];   // [B][3C][HW]
__device__ float g_attn[(size_t)CCH * BATCH * HWSZ];      // [B][C][HW]
__device__ __nv_bfloat16 g_wh[(3 + 1) * CCH * CCH];       // qkv_w then proj_w, hi
__device__ __nv_bfloat16 g_wl[(3 + 1) * CCH * CCH];       // lo

// ---------------------------------------------------------------------------
// Warp-MMA helpers (base-PTX features only: legal for compute_103)
// ---------------------------------------------------------------------------
__device__ __forceinline__ uint32_t smem_u32(const void* p) {
    uint32_t a;
    asm("{ .reg .u64 t; cvta.to.shared.u64 t, %1; cvt.u32.u64 %0, t; }" : "=r"(a) : "l"(p));
    return a;
}

#define LDSM4(r, addr) \
    asm volatile("ldmatrix.sync.aligned.m8n8.x4.shared.b16 {%0,%1,%2,%3}, [%4];" \
        : "=r"((r)[0]), "=r"((r)[1]), "=r"((r)[2]), "=r"((r)[3]) : "r"(addr))

#define LDSM4T(r, addr) \
    asm volatile("ldmatrix.sync.aligned.m8n8.x4.trans.shared.b16 {%0,%1,%2,%3}, [%4];" \
        : "=r"((r)[0]), "=r"((r)[1]), "=r"((r)[2]), "=r"((r)[3]) : "r"(addr))

#define MMA16816(d, a, b0, b1) \
    asm volatile("mma.sync.aligned.m16n8k16.row.col.f32.bf16.bf16.f32 " \
        "{%0,%1,%2,%3}, {%4,%5,%6,%7}, {%8,%9}, {%0,%1,%2,%3};" \
        : "+f"((d)[0]), "+f"((d)[1]), "+f"((d)[2]), "+f"((d)[3]) \
        : "r"((a)[0]), "r"((a)[1]), "r"((a)[2]), "r"((a)[3]), "r"(b0), "r"(b1))

__device__ __forceinline__ void split_pack(float f0, float f1, uint32_t& hi, uint32_t& lo) {
    __nv_bfloat16 h0 = __float2bfloat16(f0);
    __nv_bfloat16 h1 = __float2bfloat16(f1);
    __nv_bfloat16 l0 = __float2bfloat16(f0 - __bfloat162float(h0));
    __nv_bfloat16 l1 = __float2bfloat16(f1 - __bfloat162float(h1));
    hi = (uint32_t)__bfloat16_as_ushort(h0) | ((uint32_t)__bfloat16_as_ushort(h1) << 16);
    lo = (uint32_t)__bfloat16_as_ushort(l0) | ((uint32_t)__bfloat16_as_ushort(l1) << 16);
}

// ---------------------------------------------------------------------------
// Kernel 0: split weights into bf16 hi/lo (runs once per launch, tiny)
// ---------------------------------------------------------------------------
__global__ void wsplit_kernel(const float* __restrict__ qkv_w,
                              const float* __restrict__ proj_w,
                              __nv_bfloat16* __restrict__ wh,
                              __nv_bfloat16* __restrict__ wl)
{
    int i = blockIdx.x * 256 + threadIdx.x;
    const int nq = 3 * CCH * CCH;
    const int nt = 4 * CCH * CCH;
    if (i < nt) {
        float f = (i < nq) ? qkv_w[i] : proj_w[i - nq];
        __nv_bfloat16 h = __float2bfloat16(f);
        wh[i] = h;
        wl[i] = __float2bfloat16(f - __bfloat162float(h));
    }
}

// ---------------------------------------------------------------------------
// Kernel 1: LayerNorm2d stats -> per-(b,c) affine coefficients
// ---------------------------------------------------------------------------
__global__ void __launch_bounds__(256) ln_stats_kernel(
    const float* __restrict__ x,
    const float* __restrict__ norm_w,
    const float* __restrict__ norm_b,
    float* __restrict__ na, float* __restrict__ nb)
{
    const int bc = blockIdx.x;
    const float4* xp = (const float4*)(x + (size_t)bc * HWSZ);
    float s = 0.f, q = 0.f;
    for (int i = threadIdx.x; i < HWSZ / 4; i += 256) {
        float4 v = xp[i];
        s += v.x + v.y + v.z + v.w;
        q += v.x * v.x + v.y * v.y + v.z * v.z + v.w * v.w;
    }
    __shared__ float rs[256], rq[256];
    rs[threadIdx.x] = s; rq[threadIdx.x] = q;
    __syncthreads();
    for (int st = 128; st > 0; st >>= 1) {
        if (threadIdx.x < st) {
            rs[threadIdx.x] += rs[threadIdx.x + st];
            rq[threadIdx.x] += rq[threadIdx.x + st];
        }
        __syncthreads();
    }
    if (threadIdx.x == 0) {
        const float inv_n = 1.f / (float)HWSZ;
        float mean = rs[0] * inv_n;
        float var  = rq[0] * inv_n - mean * mean;
        int c = bc & (CCH - 1);
        float a = norm_w[c] * rsqrtf(var + EPSLN);
        na[bc] = a;
        nb[bc] = norm_b[c] - mean * a;
    }
}

// ---------------------------------------------------------------------------
// mma.sync GEMM v2 (unchanged from R4; works well)
// ---------------------------------------------------------------------------
#define WP 136
#define XP 72
#define SM_WH 0u
#define SM_WL 34816u
#define SM_XH 69632u
#define SM_XL 88064u
#define SM_TOTAL 106496u

template<int NT, bool NORM>
__global__ void __launch_bounds__(256, 2) gemm_v2_kernel(
    const float* __restrict__ X,
    const __nv_bfloat16* __restrict__ Wh,
    const __nv_bfloat16* __restrict__ Wl,
    const float* __restrict__ bias,
    float* __restrict__ Y,
    const float* __restrict__ na, const float* __restrict__ nb)
{
    extern __shared__ char smem[];
    const uint32_t sb = smem_u32(smem);
    const int tid  = threadIdx.x;
    const int wid  = tid >> 5;
    const int lane = tid & 31;
    const int wm   = wid & 3;
    const int wn   = wid >> 2;
    const int b    = blockIdx.y;
    const int pos0 = blockIdx.x * 64;

    const float* Xb = X + (size_t)b * CCH * HWSZ + pos0;
    for (int i = tid; i < 128 * 16; i += 256) {
        int c = i >> 4, p4 = (i & 15) * 4;
        float4 v = *(const float4*)(Xb + (size_t)c * HWSZ + p4);
        if (NORM) {
            float a = na[b * CCH + c], bb = nb[b * CCH + c];
            v.x = fmaf(a, v.x, bb); v.y = fmaf(a, v.y, bb);
            v.z = fmaf(a, v.z, bb); v.w = fmaf(a, v.w, bb);
        }
        uint32_t h0, l0, h1, l1;
        split_pack(v.x, v.y, h0, l0);
        split_pack(v.z, v.w, h1, l1);
        uint32_t off = (uint32_t)(c * XP + p4) * 2u;
        *(uint2*)(smem + SM_XH + off) = make_uint2(h0, h1);
        *(uint2*)(smem + SM_XL + off) = make_uint2(l0, l1);
    }

    for (int ot = 0; ot < NT; ot++) {
        const __nv_bfloat16* WhT = Wh + (size_t)ot * 128 * CCH;
        const __nv_bfloat16* WlT = Wl + (size_t)ot * 128 * CCH;
        for (int i = tid; i < 128 * 16; i += 256) {
            int o = i >> 4, c8 = (i & 15) * 8;
            uint32_t off = (uint32_t)(o * WP + c8) * 2u;
            *(uint4*)(smem + SM_WH + off) = *(const uint4*)(WhT + o * CCH + c8);
            *(uint4*)(smem + SM_WL + off) = *(const uint4*)(WlT + o * CCH + c8);
        }
        __syncthreads();

        float acc[2][4][4];
        #pragma unroll
        for (int mi = 0; mi < 2; mi++)
            #pragma unroll
            for (int nf = 0; nf < 4; nf++)
                #pragma unroll
                for (int e = 0; e < 4; e++) acc[mi][nf][e] = 0.f;

        #pragma unroll 1
        for (int term = 0; term < 3; term++) {
            const uint32_t sA = sb + ((term == 2) ? SM_WL : SM_WH);
            const uint32_t sB = sb + ((term == 1) ? SM_XL : SM_XH);
            const uint32_t aaddr = sA +
                (uint32_t)((wm * 32 + (lane & 15)) * WP + (lane >> 4) * 8) * 2u;
            const uint32_t baddr = sB +
                (uint32_t)((lane & 15) * XP + wn * 32 + ((lane >> 4) & 1) * 8) * 2u;
            #pragma unroll
            for (int ks = 0; ks < 8; ks++) {
                uint32_t a0[4], a1[4], b0[4], b1[4];
                LDSM4 (a0, aaddr + ks * 32);
                LDSM4 (a1, aaddr + 16 * WP * 2 + ks * 32);
                LDSM4T(b0, baddr + ks * 16 * XP * 2);
                LDSM4T(b1, baddr + ks * 16 * XP * 2 + 32);
                MMA16816(acc[0][0], a0, b0[0], b0[1]);
                MMA16816(acc[0][1], a0, b0[2], b0[3]);
                MMA16816(acc[0][2], a0, b1[0], b1[1]);
                MMA16816(acc[0][3], a0, b1[2], b1[3]);
                MMA16816(acc[1][0], a1, b0[0], b0[1]);
                MMA16816(acc[1][1], a1, b0[2], b0[3]);
                MMA16816(acc[1][2], a1, b1[0], b1[1]);
                MMA16816(acc[1][3], a1, b1[2], b1[3]);
            }
        }
        __syncthreads();

        #pragma unroll
        for (int mi = 0; mi < 2; mi++) {
            int r = ot * 128 + wm * 32 + mi * 16 + (lane >> 2);
            float bv0 = bias[r], bv1 = bias[r + 8];
            float* Y0 = Y + ((size_t)b * (NT * 128) + r) * HWSZ
                          + pos0 + wn * 32 + (lane & 3) * 2;
            #pragma unroll
            for (int nf = 0; nf < 4; nf++) {
                *(float2*)(Y0 + nf * 8) =
                    make_float2(acc[mi][nf][0] + bv0, acc[mi][nf][1] + bv0);
                *(float2*)(Y0 + (size_t)8 * HWSZ + nf * 8) =
                    make_float2(acc[mi][nf][2] + bv1, acc[mi][nf][3] + bv1);
            }
        }
    }
}

// ---------------------------------------------------------------------------
// Kernel 3: window attention via mma.sync, split-bf16, P kept in registers.
// Block = 128 threads, one (b, nh, nw, head). Warp w owns q rows w*16..w*16+15.
// Q,K smem [t][d] pitch 40 (ldmatrix conflict-free); V smem [d][t] pitch 72.
// ---------------------------------------------------------------------------
#define QP 40
#define VP 72
#define OP 66

__global__ void __launch_bounds__(128) attn_mma_kernel(
    const float* __restrict__ qkv,
    float* __restrict__ attn_out)
{
    __shared__ __align__(16) char sm[29696];
    __nv_bfloat16* QH = (__nv_bfloat16*)(sm);
    __nv_bfloat16* QL = (__nv_bfloat16*)(sm + 5120);
    __nv_bfloat16* KH = (__nv_bfloat16*)(sm + 10240);
    __nv_bfloat16* KL = (__nv_bfloat16*)(sm + 15360);
    __nv_bfloat16* VH = (__nv_bfloat16*)(sm + 20480);
    __nv_bfloat16* VL = (__nv_bfloat16*)(sm + 25088);
    float* OUT = (float*)sm;   // [32][66], overlaps Q (safe: reused post-barrier)

    const int bidx = blockIdx.x;
    const int head = bidx & 3;
    const int nw_  = (bidx >> 2) & 31;
    const int nh   = (bidx >> 7) & 31;
    const int b    = bidx >> 12;
    const int tid  = threadIdx.x;
    const int wid  = tid >> 5;
    const int lane = tid & 31;

    const size_t base = ((size_t)b * (3 * CCH) + head * DIMH) * HWSZ;
    const int sp0 = (nh * WS) * WW + nw_ * WS;
    const float scale = 0.1767766952966369f;   // 32^-0.5 (folded into Q)

    // --- Load + split q/k/v (q pre-scaled). Coalesced 32B row segments. ---
    for (int i = tid; i < 2048; i += 128) {
        int d = i >> 6, t = i & 63;
        int gpos = sp0 + (t >> 3) * WW + (t & 7);
        float qv = qkv[base + (size_t)d * HWSZ + gpos] * scale;
        float kv = qkv[base + (size_t)(CCH + d) * HWSZ + gpos];
        float vv = qkv[base + (size_t)(2 * CCH + d) * HWSZ + gpos];
        __nv_bfloat16 h;
        h = __float2bfloat16(qv);
        QH[t * QP + d] = h;
        QL[t * QP + d] = __float2bfloat16(qv - __bfloat162float(h));
        h = __float2bfloat16(kv);
        KH[t * QP + d] = h;
        KL[t * QP + d] = __float2bfloat16(kv - __bfloat162float(h));
        h = __float2bfloat16(vv);
        VH[d * VP + t] = h;
        VL[d * VP + t] = __float2bfloat16(vv - __bfloat162float(h));
    }
    __syncthreads();

    // --- QK^T: warp computes rows [wid*16, wid*16+16) x 64 s, 3 split terms ---
    float qacc[8][4];
    #pragma unroll
    for (int nf = 0; nf < 8; nf++)
        #pragma unroll
        for (int e = 0; e < 4; e++) qacc[nf][e] = 0.f;

    const uint32_t qhA = smem_u32(QH + (wid * 16 + (lane & 15)) * QP + (lane >> 4) * 8);
    const uint32_t khA = smem_u32(KH + (lane & 15) * QP + (lane >> 4) * 8);

    #pragma unroll
    for (int term = 0; term < 3; term++) {
        const uint32_t aA = (term == 2) ? (qhA + 5120) : qhA;
        const uint32_t bA = (term == 1) ? (khA + 5120) : khA;
        #pragma unroll
        for (int ks = 0; ks < 2; ks++) {
            uint32_t a[4];
            LDSM4(a, aA + ks * 32);
            #pragma unroll
            for (int sg = 0; sg < 4; sg++) {
                uint32_t bb[4];
                LDSM4(bb, bA + sg * 16 * QP * 2 + ks * 32);
                MMA16816(qacc[2 * sg],     a, bb[0], bb[2]);
                MMA16816(qacc[2 * sg + 1], a, bb[1], bb[3]);
            }
        }
    }

    // --- Softmax in registers. Row r=lane>>2 (c0,c1), row r+8 (c2,c3). ---
    float mx0 = -1e30f, mx1 = -1e30f;
    #pragma unroll
    for (int nf = 0; nf < 8; nf++) {
        mx0 = fmaxf(mx0, fmaxf(qacc[nf][0], qacc[nf][1]));
        mx1 = fmaxf(mx1, fmaxf(qacc[nf][2], qacc[nf][3]));
    }
    mx0 = fmaxf(mx0, __shfl_xor_sync(0xFFFFFFFFu, mx0, 1));
    mx0 = fmaxf(mx0, __shfl_xor_sync(0xFFFFFFFFu, mx0, 2));
    mx1 = fmaxf(mx1, __shfl_xor_sync(0xFFFFFFFFu, mx1, 1));
    mx1 = fmaxf(mx1, __shfl_xor_sync(0xFFFFFFFFu, mx1, 2));

    float sm0 = 0.f, sm1 = 0.f;
    #pragma unroll
    for (int nf = 0; nf < 8; nf++) {
        qacc[nf][0] = __expf(qacc[nf][0] - mx0);
        qacc[nf][1] = __expf(qacc[nf][1] - mx0);
        qacc[nf][2] = __expf(qacc[nf][2] - mx1);
        qacc[nf][3] = __expf(qacc[nf][3] - mx1);
        sm0 += qacc[nf][0] + qacc[nf][1];
        sm1 += qacc[nf][2] + qacc[nf][3];
    }
    sm0 += __shfl_xor_sync(0xFFFFFFFFu, sm0, 1);
    sm0 += __shfl_xor_sync(0xFFFFFFFFu, sm0, 2);
    sm1 += __shfl_xor_sync(0xFFFFFFFFu, sm1, 1);
    sm1 += __shfl_xor_sync(0xFFFFFFFFu, sm1, 2);
    const float inv0 = 1.f / sm0, inv1 = 1.f / sm1;

    // --- P -> split bf16 A-frags directly (acc layout == A-operand layout) ---
    uint32_t paH[4][4], paL[4][4];
    #pragma unroll
    for (int ks = 0; ks < 4; ks++) {
        int nf0 = 2 * ks, nf1 = nf0 + 1;
        split_pack(qacc[nf0][0] * inv0, qacc[nf0][1] * inv0, paH[ks][0], paL[ks][0]);
        split_pack(qacc[nf0][2] * inv1, qacc[nf0][3] * inv1, paH[ks][1], paL[ks][1]);
        split_pack(qacc[nf1][0] * inv0, qacc[nf1][1] * inv0, paH[ks][2], paL[ks][2]);
        split_pack(qacc[nf1][2] * inv1, qacc[nf1][3] * inv1, paH[ks][3], paL[ks][3]);
    }

    // --- PV: out[16 t][32 d], 3 split terms, V frags from [d][t] smem ---
    float oacc[4][4];
    #pragma unroll
    for (int nf = 0; nf < 4; nf++)
        #pragma unroll
        for (int e = 0; e < 4; e++) oacc[nf][e] = 0.f;

    const uint32_t vhA = smem_u32(VH + (lane & 15) * VP + (lane >> 4) * 8);
    #pragma unroll
    for (int ks = 0; ks < 4; ks++) {
        #pragma unroll
        for (int ng = 0; ng < 2; ng++) {
            uint32_t vh[4], vl[4];
            LDSM4(vh, vhA + ng * 16 * VP * 2 + ks * 32);
            LDSM4(vl, vhA + 4608 + ng * 16 * VP * 2 + ks * 32);
            MMA16816(oacc[2 * ng],     paH[ks], vh[0], vh[2]);
            MMA16816(oacc[2 * ng + 1], paH[ks], vh[1], vh[3]);
            MMA16816(oacc[2 * ng],     paL[ks], vh[0], vh[2]);
            MMA16816(oacc[2 * ng + 1], paL[ks], vh[1], vh[3]);
            MMA16816(oacc[2 * ng],     paH[ks], vl[0], vl[2]);
            MMA16816(oacc[2 * ng + 1], paH[ks], vl[1], vl[3]);
        }
    }

    // --- Stage transposed to [d][t], then coalesced writeback ---
    __syncthreads();
    {
        int r = lane >> 2, cb = (lane & 3) * 2;
        int t = wid * 16 + r;
        #pragma unroll
        for (int nf = 0; nf < 4; nf++) {
            int d = nf * 8 + cb;
            OUT[d * OP + t]           = oacc[nf][0];
            OUT[(d + 1) * OP + t]     = oacc[nf][1];
            OUT[d * OP + t + 8]       = oacc[nf][2];
            OUT[(d + 1) * OP + t + 8] = oacc[nf][3];
        }
    }
    __syncthreads();

    const size_t obase = ((size_t)b * CCH + head * DIMH) * HWSZ;
    for (int i = tid; i < 2048; i += 128) {
        int d = i >> 6, t = i & 63;
        int gpos = sp0 + (t >> 3) * WW + (t & 7);
        attn_out[obase + (size_t)d * HWSZ + gpos] = OUT[d * OP + t];
    }
}

// ---------------------------------------------------------------------------
// Launch
// ---------------------------------------------------------------------------
extern "C" void kernel_launch(void* const* d_in, const int* in_sizes, int n_in,
                              void* d_out, int out_size)
{
    const float* x      = (const float*)d_in[0];
    const float* norm_w = (const float*)d_in[1];
    const float* norm_b = (const float*)d_in[2];
    const float* qkv_w  = (const float*)d_in[3];
    const float* qkv_b  = (const float*)d_in[4];
    const float* proj_w = (const float*)d_in[5];
    const float* proj_b = (const float*)d_in[6];
    float* out = (float*)d_out;

    float *na, *nb, *qkv, *attn;
    __nv_bfloat16 *wh, *wl;
    cudaGetSymbolAddress((void**)&na,   g_na);
    cudaGetSymbolAddress((void**)&nb,   g_nb);
    cudaGetSymbolAddress((void**)&qkv,  g_qkv);
    cudaGetSymbolAddress((void**)&attn, g_attn);
    cudaGetSymbolAddress((void**)&wh,   g_wh);
    cudaGetSymbolAddress((void**)&wl,   g_wl);

    cudaFuncSetAttribute(gemm_v2_kernel<3, true>,
                         cudaFuncAttributeMaxDynamicSharedMemorySize, SM_TOTAL);
    cudaFuncSetAttribute(gemm_v2_kernel<1, false>,
                         cudaFuncAttributeMaxDynamicSharedMemorySize, SM_TOTAL);

    // 0) Weight split (tiny)
    wsplit_kernel<<<(4 * CCH * CCH + 255) / 256, 256>>>(qkv_w, proj_w, wh, wl);

    // 1) LayerNorm stats
    ln_stats_kernel<<<BATCH * CCH, 256>>>(x, norm_w, norm_b, na, nb);

    // 2) QKV GEMM (HMMA, fused norm)
    gemm_v2_kernel<3, true><<<dim3(HWSZ / 64, BATCH), 256, SM_TOTAL>>>(
        x, wh, wl, qkv_b, qkv, na, nb);

    // 3) Window attention (HMMA, split-bf16, register-resident P)
    attn_mma_kernel<<<BATCH * NWIN * NWIN * HEADS, 128>>>(qkv, attn);

    // 4) Projection GEMM (HMMA)
    gemm_v2_kernel<1, false><<<dim3(HWSZ / 64, BATCH), 256, SM_TOTAL>>>(
        attn, wh + 3 * CCH * CCH, wl + 3 * CCH * CCH, proj_b, out, nullptr, nullptr);
}

// round 6
// speedup vs baseline: 2.4618x; 1.1832x over previous
#include <cuda_runtime.h>
#include <cuda_bf16.h>
#include <cstdint>

// Problem constants
#define BATCH 8
#define CCH   128
#define HH    256
#define WW    256
#define HWSZ  65536
#define HEADS 4
#define DIMH  32
#define WS    8
#define NWIN  32
#define EPSLN 1e-6f

// Scratch (device globals; allocation is forbidden)
__device__ float g_na[BATCH * CCH];
__device__ float g_nb[BATCH * CCH];
__device__ float g_qkv[(size_t)3 * CCH * BATCH * HWSZ];   // [B][3C][HW]
__device__ float g_attn[(size_t)CCH * BATCH * HWSZ];      // [B][C][HW]
__device__ __nv_bfloat16 g_wh[(3 + 1) * CCH * CCH];       // qkv_w then proj_w, hi
__device__ __nv_bfloat16 g_wl[(3 + 1) * CCH * CCH];       // lo

// ---------------------------------------------------------------------------
// Warp-MMA + cp.async helpers (base-PTX features only: legal for compute_103)
// ---------------------------------------------------------------------------
__device__ __forceinline__ uint32_t smem_u32(const void* p) {
    uint32_t a;
    asm("{ .reg .u64 t; cvta.to.shared.u64 t, %1; cvt.u32.u64 %0, t; }" : "=r"(a) : "l"(p));
    return a;
}

#define LDSM4(r, addr) \
    asm volatile("ldmatrix.sync.aligned.m8n8.x4.shared.b16 {%0,%1,%2,%3}, [%4];" \
        : "=r"((r)[0]), "=r"((r)[1]), "=r"((r)[2]), "=r"((r)[3]) : "r"(addr))

#define LDSM4T(r, addr) \
    asm volatile("ldmatrix.sync.aligned.m8n8.x4.trans.shared.b16 {%0,%1,%2,%3}, [%4];" \
        : "=r"((r)[0]), "=r"((r)[1]), "=r"((r)[2]), "=r"((r)[3]) : "r"(addr))

#define MMA16816(d, a, b0, b1) \
    asm volatile("mma.sync.aligned.m16n8k16.row.col.f32.bf16.bf16.f32 " \
        "{%0,%1,%2,%3}, {%4,%5,%6,%7}, {%8,%9}, {%0,%1,%2,%3};" \
        : "+f"((d)[0]), "+f"((d)[1]), "+f"((d)[2]), "+f"((d)[3]) \
        : "r"((a)[0]), "r"((a)[1]), "r"((a)[2]), "r"((a)[3]), "r"(b0), "r"(b1))

#define CP_ASYNC16(dst, src) \
    asm volatile("cp.async.cg.shared.global [%0], [%1], 16;" :: "r"(dst), "l"(src))
#define CP_COMMIT() asm volatile("cp.async.commit_group;" ::: "memory")
#define CP_WAIT3()  asm volatile("cp.async.wait_group 3;" ::: "memory")

__device__ __forceinline__ void split_pack(float f0, float f1, uint32_t& hi, uint32_t& lo) {
    __nv_bfloat16 h0 = __float2bfloat16(f0);
    __nv_bfloat16 h1 = __float2bfloat16(f1);
    __nv_bfloat16 l0 = __float2bfloat16(f0 - __bfloat162float(h0));
    __nv_bfloat16 l1 = __float2bfloat16(f1 - __bfloat162float(h1));
    hi = (uint32_t)__bfloat16_as_ushort(h0) | ((uint32_t)__bfloat16_as_ushort(h1) << 16);
    lo = (uint32_t)__bfloat16_as_ushort(l0) | ((uint32_t)__bfloat16_as_ushort(l1) << 16);
}

__device__ __forceinline__ void split4(float4 v, uint2& h, uint2& l) {
    uint32_t h0, l0, h1, l1;
    split_pack(v.x, v.y, h0, l0);
    split_pack(v.z, v.w, h1, l1);
    h = make_uint2(h0, h1);
    l = make_uint2(l0, l1);
}

// ---------------------------------------------------------------------------
// Kernel 0: split weights into bf16 hi/lo
// ---------------------------------------------------------------------------
__global__ void wsplit_kernel(const float* __restrict__ qkv_w,
                              const float* __restrict__ proj_w,
                              __nv_bfloat16* __restrict__ wh,
                              __nv_bfloat16* __restrict__ wl)
{
    int i = blockIdx.x * 256 + threadIdx.x;
    const int nq = 3 * CCH * CCH;
    const int nt = 4 * CCH * CCH;
    if (i < nt) {
        float f = (i < nq) ? qkv_w[i] : proj_w[i - nq];
        __nv_bfloat16 h = __float2bfloat16(f);
        wh[i] = h;
        wl[i] = __float2bfloat16(f - __bfloat162float(h));
    }
}

// ---------------------------------------------------------------------------
// Kernel 1: LayerNorm2d stats -> per-(b,c) affine coefficients
// ---------------------------------------------------------------------------
__global__ void __launch_bounds__(256) ln_stats_kernel(
    const float* __restrict__ x,
    const float* __restrict__ norm_w,
    const float* __restrict__ norm_b,
    float* __restrict__ na, float* __restrict__ nb)
{
    const int bc = blockIdx.x;
    const float4* xp = (const float4*)(x + (size_t)bc * HWSZ);
    float s = 0.f, q = 0.f;
    for (int i = threadIdx.x; i < HWSZ / 4; i += 256) {
        float4 v = xp[i];
        s += v.x + v.y + v.z + v.w;
        q += v.x * v.x + v.y * v.y + v.z * v.z + v.w * v.w;
    }
    __shared__ float rs[256], rq[256];
    rs[threadIdx.x] = s; rq[threadIdx.x] = q;
    __syncthreads();
    for (int st = 128; st > 0; st >>= 1) {
        if (threadIdx.x < st) {
            rs[threadIdx.x] += rs[threadIdx.x + st];
            rq[threadIdx.x] += rq[threadIdx.x + st];
        }
        __syncthreads();
    }
    if (threadIdx.x == 0) {
        const float inv_n = 1.f / (float)HWSZ;
        float mean = rs[0] * inv_n;
        float var  = rq[0] * inv_n - mean * mean;
        int c = bc & (CCH - 1);
        float a = norm_w[c] * rsqrtf(var + EPSLN);
        na[bc] = a;
        nb[bc] = norm_b[c] - mean * a;
    }
}

// ---------------------------------------------------------------------------
// GEMM v3: cp.async chunked W pipeline + merged-term mainloop.
// CTA: NT*128 o x 64 pos, K=128. smem 104KB -> 2 CTAs/SM.
// ---------------------------------------------------------------------------
#define WP 136
#define XP 72
#define SM_WH 0u
#define SM_WL 34816u
#define SM_XH 69632u
#define SM_XL 88064u
#define SM_TOTAL 106496u

__device__ __forceinline__ void issue_chunk(uint32_t sb,
    const __nv_bfloat16* WhT, const __nv_bfloat16* WlT, int c, int tid)
{
    #pragma unroll
    for (int rep = 0; rep < 2; rep++) {
        int s = tid + rep * 256;
        int o = s >> 2, col = c * 32 + (s & 3) * 8;
        uint32_t soff = (uint32_t)(o * WP + col) * 2u;
        CP_ASYNC16(sb + SM_WH + soff, WhT + o * CCH + col);
        CP_ASYNC16(sb + SM_WL + soff, WlT + o * CCH + col);
    }
    CP_COMMIT();
}

template<int NT, bool NORM>
__global__ void __launch_bounds__(256, 2) gemm_v3_kernel(
    const float* __restrict__ X,
    const __nv_bfloat16* __restrict__ Wh,
    const __nv_bfloat16* __restrict__ Wl,
    const float* __restrict__ bias,
    float* __restrict__ Y,
    const float* __restrict__ na, const float* __restrict__ nb)
{
    extern __shared__ char smem[];
    const uint32_t sb = smem_u32(smem);
    const int tid  = threadIdx.x;
    const int wid  = tid >> 5;
    const int lane = tid & 31;
    const int wm   = wid & 3;
    const int wn   = wid >> 2;
    const int b    = blockIdx.y;
    const int pos0 = blockIdx.x * 64;

    // Prefetch first W chunks before X load so they stream concurrently.
    issue_chunk(sb, Wh, Wl, 0, tid);
    issue_chunk(sb, Wh, Wl, 1, tid);

    // X load + split: [c][pos] bf16, LN affine fused.
    const float* Xb = X + (size_t)b * CCH * HWSZ + pos0;
    for (int i = tid; i < 128 * 16; i += 256) {
        int c = i >> 4, p4 = (i & 15) * 4;
        float4 v = *(const float4*)(Xb + (size_t)c * HWSZ + p4);
        if (NORM) {
            float a = na[b * CCH + c], bb = nb[b * CCH + c];
            v.x = fmaf(a, v.x, bb); v.y = fmaf(a, v.y, bb);
            v.z = fmaf(a, v.z, bb); v.w = fmaf(a, v.w, bb);
        }
        uint2 h, l;
        split4(v, h, l);
        uint32_t off = (uint32_t)(c * XP + p4) * 2u;
        *(uint2*)(smem + SM_XH + off) = h;
        *(uint2*)(smem + SM_XL + off) = l;
    }
    issue_chunk(sb, Wh, Wl, 2, tid);
    issue_chunk(sb, Wh, Wl, 3, tid);
    __syncthreads();   // X visible to all warps

    const uint32_t aH = sb + SM_WH +
        (uint32_t)((wm * 32 + (lane & 15)) * WP + (lane >> 4) * 8) * 2u;
    const uint32_t aL = aH + (SM_WL - SM_WH);
    const uint32_t bH = sb + SM_XH +
        (uint32_t)((lane & 15) * XP + wn * 32 + ((lane >> 4) & 1) * 8) * 2u;
    const uint32_t bL = bH + (SM_XL - SM_XH);

    for (int ot = 0; ot < NT; ot++) {
        float acc[2][4][4];
        #pragma unroll
        for (int mi = 0; mi < 2; mi++)
            #pragma unroll
            for (int nf = 0; nf < 4; nf++)
                #pragma unroll
                for (int e = 0; e < 4; e++) acc[mi][nf][e] = 0.f;

        #pragma unroll
        for (int c = 0; c < 4; c++) {
            CP_WAIT3();
            __syncthreads();   // chunk (ot,c) landed; all warps aligned
            #pragma unroll
            for (int kk = 0; kk < 2; kk++) {
                const int ks = 2 * c + kk;
                uint32_t ah0[4], ah1[4], al0[4], al1[4];
                uint32_t bh0[4], bh1[4], bl0[4], bl1[4];
                LDSM4 (ah0, aH + ks * 32);
                LDSM4 (ah1, aH + 16 * WP * 2 + ks * 32);
                LDSM4 (al0, aL + ks * 32);
                LDSM4 (al1, aL + 16 * WP * 2 + ks * 32);
                LDSM4T(bh0, bH + ks * 16 * XP * 2);
                LDSM4T(bh1, bH + ks * 16 * XP * 2 + 32);
                LDSM4T(bl0, bL + ks * 16 * XP * 2);
                LDSM4T(bl1, bL + ks * 16 * XP * 2 + 32);
                // Wh x Xh
                MMA16816(acc[0][0], ah0, bh0[0], bh0[1]);
                MMA16816(acc[0][1], ah0, bh0[2], bh0[3]);
                MMA16816(acc[0][2], ah0, bh1[0], bh1[1]);
                MMA16816(acc[0][3], ah0, bh1[2], bh1[3]);
                MMA16816(acc[1][0], ah1, bh0[0], bh0[1]);
                MMA16816(acc[1][1], ah1, bh0[2], bh0[3]);
                MMA16816(acc[1][2], ah1, bh1[0], bh1[1]);
                MMA16816(acc[1][3], ah1, bh1[2], bh1[3]);
                // Wh x Xl
                MMA16816(acc[0][0], ah0, bl0[0], bl0[1]);
                MMA16816(acc[0][1], ah0, bl0[2], bl0[3]);
                MMA16816(acc[0][2], ah0, bl1[0], bl1[1]);
                MMA16816(acc[0][3], ah0, bl1[2], bl1[3]);
                MMA16816(acc[1][0], ah1, bl0[0], bl0[1]);
                MMA16816(acc[1][1], ah1, bl0[2], bl0[3]);
                MMA16816(acc[1][2], ah1, bl1[0], bl1[1]);
                MMA16816(acc[1][3], ah1, bl1[2], bl1[3]);
                // Wl x Xh
                MMA16816(acc[0][0], al0, bh0[0], bh0[1]);
                MMA16816(acc[0][1], al0, bh0[2], bh0[3]);
                MMA16816(acc[0][2], al0, bh1[0], bh1[1]);
                MMA16816(acc[0][3], al0, bh1[2], bh1[3]);
                MMA16816(acc[1][0], al1, bh0[0], bh0[1]);
                MMA16816(acc[1][1], al1, bh0[2], bh0[3]);
                MMA16816(acc[1][2], al1, bh1[0], bh1[1]);
                MMA16816(acc[1][3], al1, bh1[2], bh1[3]);
            }
            __syncthreads();   // all warps done reading chunk slot c
            if (ot + 1 < NT)
                issue_chunk(sb, Wh + (size_t)(ot + 1) * 128 * CCH,
                                Wl + (size_t)(ot + 1) * 128 * CCH, c, tid);
            else
                CP_COMMIT();   // empty group keeps wait_group accounting uniform
        }

        // Epilogue (overlaps next ot's W chunk loads)
        #pragma unroll
        for (int mi = 0; mi < 2; mi++) {
            int r = ot * 128 + wm * 32 + mi * 16 + (lane >> 2);
            float bv0 = bias[r], bv1 = bias[r + 8];
            float* Y0 = Y + ((size_t)b * (NT * 128) + r) * HWSZ
                          + pos0 + wn * 32 + (lane & 3) * 2;
            #pragma unroll
            for (int nf = 0; nf < 4; nf++) {
                *(float2*)(Y0 + nf * 8) =
                    make_float2(acc[mi][nf][0] + bv0, acc[mi][nf][1] + bv0);
                *(float2*)(Y0 + (size_t)8 * HWSZ + nf * 8) =
                    make_float2(acc[mi][nf][2] + bv1, acc[mi][nf][3] + bv1);
            }
        }
    }
}

// ---------------------------------------------------------------------------
// Kernel 3: window attention v2. All tiles [d][t] pitch 72; float4 gmem I/O.
// A/B frags for QK via ldmatrix.trans from K-major storage.
// ---------------------------------------------------------------------------
#define VP 72
#define OP 68

__global__ void __launch_bounds__(128) attn_mma_kernel(
    const float* __restrict__ qkv,
    float* __restrict__ attn_out)
{
    __shared__ __align__(16) char sm[27648];
    const uint32_t sQH = smem_u32(sm);            // [32 d][72 t] bf16, 4608 B
    const uint32_t sQL = sQH + 4608;
    const uint32_t sKH = sQH + 9216;
    const uint32_t sKL = sQH + 13824;
    const uint32_t sVH = sQH + 18432;
    const uint32_t sVL = sQH + 23040;
    float* OUT = (float*)sm;                      // [32 d][68 t] fp32, 8704 B (overlaps Q)

    const int bidx = blockIdx.x;
    const int head = bidx & 3;
    const int nw_  = (bidx >> 2) & 31;
    const int nh   = (bidx >> 7) & 31;
    const int b    = bidx >> 12;
    const int tid  = threadIdx.x;
    const int wid  = tid >> 5;
    const int lane = tid & 31;

    const size_t base = ((size_t)b * (3 * CCH) + head * DIMH) * HWSZ;
    const int sp0 = (nh * WS) * WW + nw_ * WS;
    const float scale = 0.1767766952966369f;   // 32^-0.5 folded into Q

    // --- Load q/k/v as float4, split, store [d][t] (contiguous 8B stores) ---
    #pragma unroll
    for (int j = tid; j < 512; j += 128) {
        int d = j >> 4, t0 = (j & 15) * 4;
        int gpos = sp0 + (t0 >> 3) * WW + (t0 & 7);
        uint32_t soff = (uint32_t)(d * VP + t0) * 2u;
        float4 qv = *(const float4*)(qkv + base + (size_t)d * HWSZ + gpos);
        qv.x *= scale; qv.y *= scale; qv.z *= scale; qv.w *= scale;
        uint2 h, l;
        split4(qv, h, l);
        *(uint2*)(sm + (sQH - smem_u32(sm)) + soff) = h;
        *(uint2*)(sm + (sQL - smem_u32(sm)) + soff) = l;
        float4 kv = *(const float4*)(qkv + base + (size_t)(CCH + d) * HWSZ + gpos);
        split4(kv, h, l);
        *(uint2*)(sm + (sKH - smem_u32(sm)) + soff) = h;
        *(uint2*)(sm + (sKL - smem_u32(sm)) + soff) = l;
        float4 vv = *(const float4*)(qkv + base + (size_t)(2 * CCH + d) * HWSZ + gpos);
        split4(vv, h, l);
        *(uint2*)(sm + (sVH - smem_u32(sm)) + soff) = h;
        *(uint2*)(sm + (sVL - smem_u32(sm)) + soff) = l;
    }
    __syncthreads();

    // --- QK^T: warp owns q rows t in [wid*16, wid*16+16), 3 split terms ---
    // A frags from [d][t] via trans: lanes -> (d=(lane&7)+(lane>>4)*8, t=t0+((lane>>3)&1)*8)
    const uint32_t aoffQ = (uint32_t)(((lane & 7) + (lane >> 4) * 8) * VP
                                      + wid * 16 + ((lane >> 3) & 1) * 8) * 2u;
    // B frags (K) from [d][s] via trans: (d=(lane&7)+((lane>>3)&1)*8, s=(lane>>4)*8)
    const uint32_t boffK = (uint32_t)(((lane & 7) + ((lane >> 3) & 1) * 8) * VP
                                      + (lane >> 4) * 8) * 2u;

    float qacc[8][4];
    #pragma unroll
    for (int nf = 0; nf < 8; nf++)
        #pragma unroll
        for (int e = 0; e < 4; e++) qacc[nf][e] = 0.f;

    #pragma unroll
    for (int term = 0; term < 3; term++) {
        const uint32_t aA = ((term == 2) ? sQL : sQH) + aoffQ;
        const uint32_t bA = ((term == 1) ? sKL : sKH) + boffK;
        #pragma unroll
        for (int ks = 0; ks < 2; ks++) {
            uint32_t a[4];
            LDSM4T(a, aA + ks * 16 * VP * 2);
            #pragma unroll
            for (int sg = 0; sg < 4; sg++) {
                uint32_t bb[4];
                LDSM4T(bb, bA + (uint32_t)(sg * 16) * 2u + ks * 16 * VP * 2);
                MMA16816(qacc[2 * sg],     a, bb[0], bb[1]);
                MMA16816(qacc[2 * sg + 1], a, bb[2], bb[3]);
            }
        }
    }

    // --- Softmax in registers (rows r=lane>>2 and r+8, spread over 4 lanes) ---
    float mx0 = -1e30f, mx1 = -1e30f;
    #pragma unroll
    for (int nf = 0; nf < 8; nf++) {
        mx0 = fmaxf(mx0, fmaxf(qacc[nf][0], qacc[nf][1]));
        mx1 = fmaxf(mx1, fmaxf(qacc[nf][2], qacc[nf][3]));
    }
    mx0 = fmaxf(mx0, __shfl_xor_sync(0xFFFFFFFFu, mx0, 1));
    mx0 = fmaxf(mx0, __shfl_xor_sync(0xFFFFFFFFu, mx0, 2));
    mx1 = fmaxf(mx1, __shfl_xor_sync(0xFFFFFFFFu, mx1, 1));
    mx1 = fmaxf(mx1, __shfl_xor_sync(0xFFFFFFFFu, mx1, 2));

    float sm0 = 0.f, sm1 = 0.f;
    #pragma unroll
    for (int nf = 0; nf < 8; nf++) {
        qacc[nf][0] = __expf(qacc[nf][0] - mx0);
        qacc[nf][1] = __expf(qacc[nf][1] - mx0);
        qacc[nf][2] = __expf(qacc[nf][2] - mx1);
        qacc[nf][3] = __expf(qacc[nf][3] - mx1);
        sm0 += qacc[nf][0] + qacc[nf][1];
        sm1 += qacc[nf][2] + qacc[nf][3];
    }
    sm0 += __shfl_xor_sync(0xFFFFFFFFu, sm0, 1);
    sm0 += __shfl_xor_sync(0xFFFFFFFFu, sm0, 2);
    sm1 += __shfl_xor_sync(0xFFFFFFFFu, sm1, 1);
    sm1 += __shfl_xor_sync(0xFFFFFFFFu, sm1, 2);
    const float inv0 = 1.f / sm0, inv1 = 1.f / sm1;

    // --- P -> split bf16 A-frags (acc layout == A-operand layout) ---
    uint32_t paH[4][4], paL[4][4];
    #pragma unroll
    for (int ks = 0; ks < 4; ks++) {
        int nf0 = 2 * ks, nf1 = nf0 + 1;
        split_pack(qacc[nf0][0] * inv0, qacc[nf0][1] * inv0, paH[ks][0], paL[ks][0]);
        split_pack(qacc[nf0][2] * inv1, qacc[nf0][3] * inv1, paH[ks][1], paL[ks][1]);
        split_pack(qacc[nf1][0] * inv0, qacc[nf1][1] * inv0, paH[ks][2], paL[ks][2]);
        split_pack(qacc[nf1][2] * inv1, qacc[nf1][3] * inv1, paH[ks][3], paL[ks][3]);
    }

    // --- PV: out[16 t][32 d], V [d][t] non-trans B frags ---
    float oacc[4][4];
    #pragma unroll
    for (int nf = 0; nf < 4; nf++)
        #pragma unroll
        for (int e = 0; e < 4; e++) oacc[nf][e] = 0.f;

    const uint32_t vA = sVH + (uint32_t)((lane & 15) * VP + (lane >> 4) * 8) * 2u;
    #pragma unroll
    for (int ks = 0; ks < 4; ks++) {
        #pragma unroll
        for (int ng = 0; ng < 2; ng++) {
            uint32_t vh[4], vl[4];
            LDSM4(vh, vA + ng * 16 * VP * 2 + ks * 32);
            LDSM4(vl, vA + 4608 + ng * 16 * VP * 2 + ks * 32);
            MMA16816(oacc[2 * ng],     paH[ks], vh[0], vh[2]);
            MMA16816(oacc[2 * ng + 1], paH[ks], vh[1], vh[3]);
            MMA16816(oacc[2 * ng],     paL[ks], vh[0], vh[2]);
            MMA16816(oacc[2 * ng + 1], paL[ks], vh[1], vh[3]);
            MMA16816(oacc[2 * ng],     paH[ks], vl[0], vl[2]);
            MMA16816(oacc[2 * ng + 1], paH[ks], vl[1], vl[3]);
        }
    }

    // --- Stage [d][t] then float4 coalesced writeback ---
    __syncthreads();
    {
        int r = lane >> 2, cb = (lane & 3) * 2;
        int t = wid * 16 + r;
        #pragma unroll
        for (int nf = 0; nf < 4; nf++) {
            int d = nf * 8 + cb;
            OUT[d * OP + t]           = oacc[nf][0];
            OUT[(d + 1) * OP + t]     = oacc[nf][1];
            OUT[d * OP + t + 8]       = oacc[nf][2];
            OUT[(d + 1) * OP + t + 8] = oacc[nf][3];
        }
    }
    __syncthreads();

    const size_t obase = ((size_t)b * CCH + head * DIMH) * HWSZ;
    #pragma unroll
    for (int j = tid; j < 512; j += 128) {
        int d = j >> 4, t0 = (j & 15) * 4;
        int gpos = sp0 + (t0 >> 3) * WW + (t0 & 7);
        *(float4*)(attn_out + obase + (size_t)d * HWSZ + gpos) =
            *(const float4*)&OUT[d * OP + t0];
    }
}

// ---------------------------------------------------------------------------
// Launch
// ---------------------------------------------------------------------------
extern "C" void kernel_launch(void* const* d_in, const int* in_sizes, int n_in,
                              void* d_out, int out_size)
{
    const float* x      = (const float*)d_in[0];
    const float* norm_w = (const float*)d_in[1];
    const float* norm_b = (const float*)d_in[2];
    const float* qkv_w  = (const float*)d_in[3];
    const float* qkv_b  = (const float*)d_in[4];
    const float* proj_w = (const float*)d_in[5];
    const float* proj_b = (const float*)d_in[6];
    float* out = (float*)d_out;

    float *na, *nb, *qkv, *attn;
    __nv_bfloat16 *wh, *wl;
    cudaGetSymbolAddress((void**)&na,   g_na);
    cudaGetSymbolAddress((void**)&nb,   g_nb);
    cudaGetSymbolAddress((void**)&qkv,  g_qkv);
    cudaGetSymbolAddress((void**)&attn, g_attn);
    cudaGetSymbolAddress((void**)&wh,   g_wh);
    cudaGetSymbolAddress((void**)&wl,   g_wl);

    cudaFuncSetAttribute(gemm_v3_kernel<3, true>,
                         cudaFuncAttributeMaxDynamicSharedMemorySize, SM_TOTAL);
    cudaFuncSetAttribute(gemm_v3_kernel<1, false>,
                         cudaFuncAttributeMaxDynamicSharedMemorySize, SM_TOTAL);

    // 0) Weight split (tiny)
    wsplit_kernel<<<(4 * CCH * CCH + 255) / 256, 256>>>(qkv_w, proj_w, wh, wl);

    // 1) LayerNorm stats
    ln_stats_kernel<<<BATCH * CCH, 256>>>(x, norm_w, norm_b, na, nb);

    // 2) QKV GEMM (HMMA, cp.async W pipeline, fused norm)
    gemm_v3_kernel<3, true><<<dim3(HWSZ / 64, BATCH), 256, SM_TOTAL>>>(
        x, wh, wl, qkv_b, qkv, na, nb);

    // 3) Window attention (HMMA, [d][t] tiles, float4 I/O)
    attn_mma_kernel<<<BATCH * NWIN * NWIN * HEADS, 128>>>(qkv, attn);

    // 4) Projection GEMM (HMMA, cp.async W pipeline)
    gemm_v3_kernel<1, false><<<dim3(HWSZ / 64, BATCH), 256, SM_TOTAL>>>(
        attn, wh + 3 * CCH * CCH, wl + 3 * CCH * CCH, proj_b, out, nullptr, nullptr);
}

// round 7
// speedup vs baseline: 2.8548x; 1.1596x over previous
#include <cuda_runtime.h>
#include <cuda_fp16.h>
#include <cstdint>

// Problem constants
#define BATCH 8
#define CCH   128
#define HH    256
#define WW    256
#define HWSZ  65536
#define HEADS 4
#define DIMH  32
#define WS    8
#define NWIN  32
#define EPSLN 1e-6f

// Scratch (device globals; allocation is forbidden)
__device__ float g_na[BATCH * CCH];
__device__ float g_nb[BATCH * CCH];
__device__ __half g_qkvh[(size_t)3 * CCH * BATCH * HWSZ];  // fp16 [B][3C][HW]
__device__ __half g_attnh[(size_t)CCH * BATCH * HWSZ];     // fp16 [B][C][HW]
__device__ __half g_wf[(3 + 1) * CCH * CCH];               // qkv_w then proj_w fp16

// ---------------------------------------------------------------------------
// Helpers (base-PTX features only: legal for compute_103)
// ---------------------------------------------------------------------------
__device__ __forceinline__ uint32_t smem_u32(const void* p) {
    uint32_t a;
    asm("{ .reg .u64 t; cvta.to.shared.u64 t, %1; cvt.u32.u64 %0, t; }" : "=r"(a) : "l"(p));
    return a;
}

#define LDSM4(r, addr) \
    asm volatile("ldmatrix.sync.aligned.m8n8.x4.shared.b16 {%0,%1,%2,%3}, [%4];" \
        : "=r"((r)[0]), "=r"((r)[1]), "=r"((r)[2]), "=r"((r)[3]) : "r"(addr))

#define LDSM4T(r, addr) \
    asm volatile("ldmatrix.sync.aligned.m8n8.x4.trans.shared.b16 {%0,%1,%2,%3}, [%4];" \
        : "=r"((r)[0]), "=r"((r)[1]), "=r"((r)[2]), "=r"((r)[3]) : "r"(addr))

#define MMAF16(d, a, b0, b1) \
    asm volatile("mma.sync.aligned.m16n8k16.row.col.f32.f16.f16.f32 " \
        "{%0,%1,%2,%3}, {%4,%5,%6,%7}, {%8,%9}, {%0,%1,%2,%3};" \
        : "+f"((d)[0]), "+f"((d)[1]), "+f"((d)[2]), "+f"((d)[3]) \
        : "r"((a)[0]), "r"((a)[1]), "r"((a)[2]), "r"((a)[3]), "r"(b0), "r"(b1))

#define CP_ASYNC16(dst, src) \
    asm volatile("cp.async.cg.shared.global [%0], [%1], 16;" :: "r"(dst), "l"(src))
#define CP_COMMIT() asm volatile("cp.async.commit_group;" ::: "memory")
#define CP_WAIT3()  asm volatile("cp.async.wait_group 3;" ::: "memory")

__device__ __forceinline__ uint32_t h2u(__half2 h) {
    uint32_t u;
    *(__half2*)&u = h;
    return u;
}

// ---------------------------------------------------------------------------
// Kernel 0: convert weights to fp16
// ---------------------------------------------------------------------------
__global__ void wconv_kernel(const float* __restrict__ qkv_w,
                             const float* __restrict__ proj_w,
                             __half* __restrict__ wf)
{
    int i = blockIdx.x * 256 + threadIdx.x;
    const int nq = 3 * CCH * CCH;
    const int nt = 4 * CCH * CCH;
    if (i < nt)
        wf[i] = __float2half_rn((i < nq) ? qkv_w[i] : proj_w[i - nq]);
}

// ---------------------------------------------------------------------------
// Kernel 1: LayerNorm2d stats -> per-(b,c) affine coefficients
// ---------------------------------------------------------------------------
__global__ void __launch_bounds__(256) ln_stats_kernel(
    const float* __restrict__ x,
    const float* __restrict__ norm_w,
    const float* __restrict__ norm_b,
    float* __restrict__ na, float* __restrict__ nb)
{
    const int bc = blockIdx.x;
    const float4* xp = (const float4*)(x + (size_t)bc * HWSZ);
    float s = 0.f, q = 0.f;
    for (int i = threadIdx.x; i < HWSZ / 4; i += 256) {
        float4 v = xp[i];
        s += v.x + v.y + v.z + v.w;
        q += v.x * v.x + v.y * v.y + v.z * v.z + v.w * v.w;
    }
    __shared__ float rs[256], rq[256];
    rs[threadIdx.x] = s; rq[threadIdx.x] = q;
    __syncthreads();
    for (int st = 128; st > 0; st >>= 1) {
        if (threadIdx.x < st) {
            rs[threadIdx.x] += rs[threadIdx.x + st];
            rq[threadIdx.x] += rq[threadIdx.x + st];
        }
        __syncthreads();
    }
    if (threadIdx.x == 0) {
        const float inv_n = 1.f / (float)HWSZ;
        float mean = rs[0] * inv_n;
        float var  = rq[0] * inv_n - mean * mean;
        int c = bc & (CCH - 1);
        float a = norm_w[c] * rsqrtf(var + EPSLN);
        na[bc] = a;
        nb[bc] = norm_b[c] - mean * a;
    }
}

// ---------------------------------------------------------------------------
// fp16 single-pass GEMM: Y[b,o,pos] = sum_c W[o,c]*X[b,c,pos] + bias[o]
// CTA: NT*128 o x 128 pos. smem = W[128][136] + X[128][136] fp16 = 68KB, 2/SM.
// 8 warps: wm=wid&3 (32 o), wn=wid>>2 (64 pos). cp.async chunked W pipeline.
// ---------------------------------------------------------------------------
#define GP 136         // pitch (halves); 272B row stride -> conflict-free LDSM
#define SW_OFF 0u
#define SX_OFF 34816u
#define SM_TOTAL 69632u

__device__ __forceinline__ void issue_chunk_f16(uint32_t sb,
    const __half* Wt, int c, int tid)
{
    #pragma unroll
    for (int rep = 0; rep < 2; rep++) {
        int s = tid + rep * 256;
        int o = s >> 2, col = c * 32 + (s & 3) * 8;
        CP_ASYNC16(sb + SW_OFF + (uint32_t)(o * GP + col) * 2u, Wt + o * CCH + col);
    }
    CP_COMMIT();
}

template<int NT, bool NORM, bool INF16, bool OUTF16>
__global__ void __launch_bounds__(256, 2) gemm_f16_kernel(
    const void* __restrict__ Xv,        // fp32 [B][128][HW] or fp16
    const __half* __restrict__ Wf,      // [NT*128][128]
    const float* __restrict__ bias,
    void* __restrict__ Yv,              // fp16 or fp32 [B][NT*128][HW]
    const float* __restrict__ na, const float* __restrict__ nb)
{
    extern __shared__ char smem[];
    const uint32_t sb = smem_u32(smem);
    const int tid  = threadIdx.x;
    const int wid  = tid >> 5;
    const int lane = tid & 31;
    const int wm   = wid & 3;
    const int wn   = wid >> 2;
    const int b    = blockIdx.y;
    const int pos0 = blockIdx.x * 128;

    issue_chunk_f16(sb, Wf, 0, tid);
    issue_chunk_f16(sb, Wf, 1, tid);

    // --- X staging: [c][pos] fp16 tile ---
    if (INF16) {
        const __half* Xh = (const __half*)Xv + (size_t)b * CCH * HWSZ + pos0;
        for (int i = tid; i < 128 * 16; i += 256) {
            int c = i >> 4, p8 = (i & 15) * 8;
            *(uint4*)(smem + SX_OFF + (uint32_t)(c * GP + p8) * 2u) =
                *(const uint4*)(Xh + (size_t)c * HWSZ + p8);
        }
    } else {
        const float* Xf = (const float*)Xv + (size_t)b * CCH * HWSZ + pos0;
        for (int i = tid; i < 128 * 32; i += 256) {
            int c = i >> 5, p4 = (i & 31) * 4;
            float4 v = *(const float4*)(Xf + (size_t)c * HWSZ + p4);
            if (NORM) {
                float a = na[b * CCH + c], bb = nb[b * CCH + c];
                v.x = fmaf(a, v.x, bb); v.y = fmaf(a, v.y, bb);
                v.z = fmaf(a, v.z, bb); v.w = fmaf(a, v.w, bb);
            }
            uint32_t off = SX_OFF + (uint32_t)(c * GP + p4) * 2u;
            *(uint2*)(smem + off) = make_uint2(
                h2u(__floats2half2_rn(v.x, v.y)), h2u(__floats2half2_rn(v.z, v.w)));
        }
    }
    issue_chunk_f16(sb, Wf, 2, tid);
    issue_chunk_f16(sb, Wf, 3, tid);
    __syncthreads();

    const uint32_t aaddr = sb + SW_OFF +
        (uint32_t)((wm * 32 + (lane & 15)) * GP + (lane >> 4) * 8) * 2u;
    const uint32_t baddr = sb + SX_OFF +
        (uint32_t)((lane & 15) * GP + wn * 64 + ((lane >> 4) & 1) * 8) * 2u;

    for (int ot = 0; ot < NT; ot++) {
        float acc[2][8][4];
        #pragma unroll
        for (int mi = 0; mi < 2; mi++)
            #pragma unroll
            for (int nf = 0; nf < 8; nf++)
                #pragma unroll
                for (int e = 0; e < 4; e++) acc[mi][nf][e] = 0.f;

        #pragma unroll
        for (int c = 0; c < 4; c++) {
            CP_WAIT3();
            __syncthreads();
            #pragma unroll
            for (int kk = 0; kk < 2; kk++) {
                const int ks = 2 * c + kk;
                uint32_t a0[4], a1[4];
                LDSM4(a0, aaddr + ks * 32);
                LDSM4(a1, aaddr + 16 * GP * 2 + ks * 32);
                #pragma unroll
                for (int g = 0; g < 4; g++) {
                    uint32_t bg[4];
                    LDSM4T(bg, baddr + ks * 16 * GP * 2 + g * 32);
                    MMAF16(acc[0][2 * g],     a0, bg[0], bg[1]);
                    MMAF16(acc[0][2 * g + 1], a0, bg[2], bg[3]);
                    MMAF16(acc[1][2 * g],     a1, bg[0], bg[1]);
                    MMAF16(acc[1][2 * g + 1], a1, bg[2], bg[3]);
                }
            }
            __syncthreads();
            if (ot + 1 < NT)
                issue_chunk_f16(sb, Wf + (size_t)(ot + 1) * 128 * CCH, c, tid);
            else
                CP_COMMIT();
        }

        // Epilogue
        #pragma unroll
        for (int mi = 0; mi < 2; mi++) {
            int r = ot * 128 + wm * 32 + mi * 16 + (lane >> 2);
            float bv0 = bias[r], bv1 = bias[r + 8];
            size_t rowoff = ((size_t)b * (NT * 128) + r) * HWSZ
                            + pos0 + wn * 64 + (lane & 3) * 2;
            if (OUTF16) {
                __half* Y0 = (__half*)Yv + rowoff;
                #pragma unroll
                for (int nf = 0; nf < 8; nf++) {
                    *(uint32_t*)(Y0 + nf * 8) = h2u(
                        __floats2half2_rn(acc[mi][nf][0] + bv0, acc[mi][nf][1] + bv0));
                    *(uint32_t*)(Y0 + (size_t)8 * HWSZ + nf * 8) = h2u(
                        __floats2half2_rn(acc[mi][nf][2] + bv1, acc[mi][nf][3] + bv1));
                }
            } else {
                float* Y0 = (float*)Yv + rowoff;
                #pragma unroll
                for (int nf = 0; nf < 8; nf++) {
                    *(float2*)(Y0 + nf * 8) =
                        make_float2(acc[mi][nf][0] + bv0, acc[mi][nf][1] + bv0);
                    *(float2*)(Y0 + (size_t)8 * HWSZ + nf * 8) =
                        make_float2(acc[mi][nf][2] + bv1, acc[mi][nf][3] + bv1);
                }
            }
        }
    }
}

// ---------------------------------------------------------------------------
// Kernel 3: window attention, all-fp16 single-pass. Tiles [d][t] pitch 72.
// Scale folded into exp (softmax(s*scale) via exp((s-max)*scale)).
// ---------------------------------------------------------------------------
#define VP 72

__global__ void __launch_bounds__(128) attn_f16_kernel(
    const __half* __restrict__ qkv,
    __half* __restrict__ attn_out)
{
    __shared__ __align__(16) __half sQ[32 * VP];
    __shared__ __align__(16) __half sK[32 * VP];
    __shared__ __align__(16) __half sV[32 * VP];
    __half* OUT = sQ;   // reuse post-barrier

    const int bidx = blockIdx.x;
    const int head = bidx & 3;
    const int nw_  = (bidx >> 2) & 31;
    const int nh   = (bidx >> 7) & 31;
    const int b    = bidx >> 12;
    const int tid  = threadIdx.x;
    const int wid  = tid >> 5;
    const int lane = tid & 31;

    const size_t base = ((size_t)b * (3 * CCH) + head * DIMH) * HWSZ;
    const int sp0 = (nh * WS) * WW + nw_ * WS;
    const float scale = 0.1767766952966369f;   // 32^-0.5

    // --- Straight fp16 copies gmem -> smem [d][t], uint4 (8 t) segments ---
    #pragma unroll
    for (int j = tid; j < 256; j += 128) {
        int d = j >> 3, tr = j & 7;
        size_t g = base + (size_t)d * HWSZ + sp0 + tr * WW;
        int so = d * VP + tr * 8;
        *(uint4*)(sQ + so) = *(const uint4*)(qkv + g);
        *(uint4*)(sK + so) = *(const uint4*)(qkv + g + (size_t)CCH * HWSZ);
        *(uint4*)(sV + so) = *(const uint4*)(qkv + g + (size_t)(2 * CCH) * HWSZ);
    }
    __syncthreads();

    // --- QK^T: warp owns q rows [wid*16, wid*16+16) x all 64 s ---
    const uint32_t aA = smem_u32(sQ) +
        (uint32_t)(((lane & 7) + (lane >> 4) * 8) * VP
                   + wid * 16 + ((lane >> 3) & 1) * 8) * 2u;
    const uint32_t bA = smem_u32(sK) +
        (uint32_t)(((lane & 7) + ((lane >> 3) & 1) * 8) * VP + (lane >> 4) * 8) * 2u;

    float qacc[8][4];
    #pragma unroll
    for (int nf = 0; nf < 8; nf++)
        #pragma unroll
        for (int e = 0; e < 4; e++) qacc[nf][e] = 0.f;

    #pragma unroll
    for (int ks = 0; ks < 2; ks++) {
        uint32_t a[4];
        LDSM4T(a, aA + ks * 16 * VP * 2);
        #pragma unroll
        for (int sg = 0; sg < 4; sg++) {
            uint32_t bb[4];
            LDSM4T(bb, bA + sg * 32 + ks * 16 * VP * 2);
            MMAF16(qacc[2 * sg],     a, bb[0], bb[1]);
            MMAF16(qacc[2 * sg + 1], a, bb[2], bb[3]);
        }
    }

    // --- Softmax in registers (scale folded post-max) ---
    float mx0 = -1e30f, mx1 = -1e30f;
    #pragma unroll
    for (int nf = 0; nf < 8; nf++) {
        mx0 = fmaxf(mx0, fmaxf(qacc[nf][0], qacc[nf][1]));
        mx1 = fmaxf(mx1, fmaxf(qacc[nf][2], qacc[nf][3]));
    }
    mx0 = fmaxf(mx0, __shfl_xor_sync(0xFFFFFFFFu, mx0, 1));
    mx0 = fmaxf(mx0, __shfl_xor_sync(0xFFFFFFFFu, mx0, 2));
    mx1 = fmaxf(mx1, __shfl_xor_sync(0xFFFFFFFFu, mx1, 1));
    mx1 = fmaxf(mx1, __shfl_xor_sync(0xFFFFFFFFu, mx1, 2));

    float sm0 = 0.f, sm1 = 0.f;
    #pragma unroll
    for (int nf = 0; nf < 8; nf++) {
        qacc[nf][0] = __expf((qacc[nf][0] - mx0) * scale);
        qacc[nf][1] = __expf((qacc[nf][1] - mx0) * scale);
        qacc[nf][2] = __expf((qacc[nf][2] - mx1) * scale);
        qacc[nf][3] = __expf((qacc[nf][3] - mx1) * scale);
        sm0 += qacc[nf][0] + qacc[nf][1];
        sm1 += qacc[nf][2] + qacc[nf][3];
    }
    sm0 += __shfl_xor_sync(0xFFFFFFFFu, sm0, 1);
    sm0 += __shfl_xor_sync(0xFFFFFFFFu, sm0, 2);
    sm1 += __shfl_xor_sync(0xFFFFFFFFu, sm1, 1);
    sm1 += __shfl_xor_sync(0xFFFFFFFFu, sm1, 2);
    const float inv0 = 1.f / sm0, inv1 = 1.f / sm1;

    // --- P -> fp16 A-frags (acc layout == A-operand layout) ---
    uint32_t pa[4][4];
    #pragma unroll
    for (int ks = 0; ks < 4; ks++) {
        int nf0 = 2 * ks, nf1 = nf0 + 1;
        pa[ks][0] = h2u(__floats2half2_rn(qacc[nf0][0] * inv0, qacc[nf0][1] * inv0));
        pa[ks][1] = h2u(__floats2half2_rn(qacc[nf0][2] * inv1, qacc[nf0][3] * inv1));
        pa[ks][2] = h2u(__floats2half2_rn(qacc[nf1][0] * inv0, qacc[nf1][1] * inv0));
        pa[ks][3] = h2u(__floats2half2_rn(qacc[nf1][2] * inv1, qacc[nf1][3] * inv1));
    }

    // --- PV: out[16 t][32 d] ---
    float oacc[4][4];
    #pragma unroll
    for (int nf = 0; nf < 4; nf++)
        #pragma unroll
        for (int e = 0; e < 4; e++) oacc[nf][e] = 0.f;

    const uint32_t vA = smem_u32(sV) +
        (uint32_t)((lane & 15) * VP + (lane >> 4) * 8) * 2u;
    #pragma unroll
    for (int ks = 0; ks < 4; ks++) {
        #pragma unroll
        for (int ng = 0; ng < 2; ng++) {
            uint32_t vh[4];
            LDSM4(vh, vA + ng * 16 * VP * 2 + ks * 32);
            MMAF16(oacc[2 * ng],     pa[ks], vh[0], vh[2]);
            MMAF16(oacc[2 * ng + 1], pa[ks], vh[1], vh[3]);
        }
    }

    // --- Stage fp16 [d][t], then uint4 coalesced writeback ---
    __syncthreads();
    {
        int r = lane >> 2, cb = (lane & 3) * 2;
        int t = wid * 16 + r;
        #pragma unroll
        for (int nf = 0; nf < 4; nf++) {
            int d = nf * 8 + cb;
            OUT[d * VP + t]           = __float2half_rn(oacc[nf][0]);
            OUT[(d + 1) * VP + t]     = __float2half_rn(oacc[nf][1]);
            OUT[d * VP + t + 8]       = __float2half_rn(oacc[nf][2]);
            OUT[(d + 1) * VP + t + 8] = __float2half_rn(oacc[nf][3]);
        }
    }
    __syncthreads();

    const size_t obase = ((size_t)b * CCH + head * DIMH) * HWSZ;
    #pragma unroll
    for (int j = tid; j < 256; j += 128) {
        int d = j >> 3, tr = j & 7;
        *(uint4*)(attn_out + obase + (size_t)d * HWSZ + sp0 + tr * WW) =
            *(const uint4*)(OUT + d * VP + tr * 8);
    }
}

// ---------------------------------------------------------------------------
// Launch
// ---------------------------------------------------------------------------
extern "C" void kernel_launch(void* const* d_in, const int* in_sizes, int n_in,
                              void* d_out, int out_size)
{
    const float* x      = (const float*)d_in[0];
    const float* norm_w = (const float*)d_in[1];
    const float* norm_b = (const float*)d_in[2];
    const float* qkv_w  = (const float*)d_in[3];
    const float* qkv_b  = (const float*)d_in[4];
    const float* proj_w = (const float*)d_in[5];
    const float* proj_b = (const float*)d_in[6];
    float* out = (float*)d_out;

    float *na, *nb;
    __half *qkvh, *attnh, *wf;
    cudaGetSymbolAddress((void**)&na,    g_na);
    cudaGetSymbolAddress((void**)&nb,    g_nb);
    cudaGetSymbolAddress((void**)&qkvh,  g_qkvh);
    cudaGetSymbolAddress((void**)&attnh, g_attnh);
    cudaGetSymbolAddress((void**)&wf,    g_wf);

    cudaFuncSetAttribute((const void*)gemm_f16_kernel<3, true, false, true>,
                         cudaFuncAttributeMaxDynamicSharedMemorySize, SM_TOTAL);
    cudaFuncSetAttribute((const void*)gemm_f16_kernel<1, false, true, false>,
                         cudaFuncAttributeMaxDynamicSharedMemorySize, SM_TOTAL);

    // 0) Weight convert (tiny)
    wconv_kernel<<<(4 * CCH * CCH + 255) / 256, 256>>>(qkv_w, proj_w, wf);

    // 1) LayerNorm stats
    ln_stats_kernel<<<BATCH * CCH, 256>>>(x, norm_w, norm_b, na, nb);

    // 2) QKV GEMM: fp32 in (LN fused), fp16 out
    gemm_f16_kernel<3, true, false, true><<<dim3(HWSZ / 128, BATCH), 256, SM_TOTAL>>>(
        x, wf, qkv_b, qkvh, na, nb);

    // 3) Window attention (all fp16)
    attn_f16_kernel<<<BATCH * NWIN * NWIN * HEADS, 128>>>(qkvh, attnh);

    // 4) Projection GEMM: fp16 in, fp32 out
    gemm_f16_kernel<1, false, true, false><<<dim3(HWSZ / 128, BATCH), 256, SM_TOTAL>>>(
        attnh, wf + 3 * CCH * CCH, proj_b, out, nullptr, nullptr);
}

// round 8
// speedup vs baseline: 4.0808x; 1.4295x over previous
#include <cuda_runtime.h>
#include <cuda_fp16.h>
#include <cstdint>

// Problem constants
#define BATCH 8
#define CCH   128
#define HH    256
#define WW    256
#define HWSZ  65536
#define HEADS 4
#define DIMH  32
#define WS    8
#define NWIN  32
#define EPSLN 1e-6f

// Scratch (device globals; allocation is forbidden)
__device__ float g_na[BATCH * CCH];
__device__ float g_nb[BATCH * CCH];
__device__ __half g_qkvh[(size_t)3 * CCH * BATCH * HWSZ];  // fp16 [B][3C][HW]
__device__ __half g_attnh[(size_t)CCH * BATCH * HWSZ];     // fp16 [B][C][HW]
__device__ __half g_wf[(3 + 1) * CCH * CCH];               // qkv_w then proj_w fp16

// ---------------------------------------------------------------------------
// Helpers (base-PTX features only: legal for compute_103)
// ---------------------------------------------------------------------------
__device__ __forceinline__ uint32_t smem_u32(const void* p) {
    uint32_t a;
    asm("{ .reg .u64 t; cvta.to.shared.u64 t, %1; cvt.u32.u64 %0, t; }" : "=r"(a) : "l"(p));
    return a;
}

#define LDSM4(r, addr) \
    asm volatile("ldmatrix.sync.aligned.m8n8.x4.shared.b16 {%0,%1,%2,%3}, [%4];" \
        : "=r"((r)[0]), "=r"((r)[1]), "=r"((r)[2]), "=r"((r)[3]) : "r"(addr))

#define LDSM4T(r, addr) \
    asm volatile("ldmatrix.sync.aligned.m8n8.x4.trans.shared.b16 {%0,%1,%2,%3}, [%4];" \
        : "=r"((r)[0]), "=r"((r)[1]), "=r"((r)[2]), "=r"((r)[3]) : "r"(addr))

#define MMAF16(d, a, b0, b1) \
    asm volatile("mma.sync.aligned.m16n8k16.row.col.f32.f16.f16.f32 " \
        "{%0,%1,%2,%3}, {%4,%5,%6,%7}, {%8,%9}, {%0,%1,%2,%3};" \
        : "+f"((d)[0]), "+f"((d)[1]), "+f"((d)[2]), "+f"((d)[3]) \
        : "r"((a)[0]), "r"((a)[1]), "r"((a)[2]), "r"((a)[3]), "r"(b0), "r"(b1))

#define CP_ASYNC16(dst, src) \
    asm volatile("cp.async.cg.shared.global [%0], [%1], 16;" :: "r"(dst), "l"(src))
#define CP_COMMIT() asm volatile("cp.async.commit_group;" ::: "memory")
#define CP_WAIT1()  asm volatile("cp.async.wait_group 1;" ::: "memory")

__device__ __forceinline__ uint32_t h2u(__half2 h) {
    uint32_t u;
    *(__half2*)&u = h;
    return u;
}

// ---------------------------------------------------------------------------
// Kernel 0: convert weights to fp16
// ---------------------------------------------------------------------------
__global__ void wconv_kernel(const float* __restrict__ qkv_w,
                             const float* __restrict__ proj_w,
                             __half* __restrict__ wf)
{
    int i = blockIdx.x * 256 + threadIdx.x;
    const int nq = 3 * CCH * CCH;
    const int nt = 4 * CCH * CCH;
    if (i < nt)
        wf[i] = __float2half_rn((i < nq) ? qkv_w[i] : proj_w[i - nq]);
}

// ---------------------------------------------------------------------------
// Kernel 1: LayerNorm2d stats -> per-(b,c) affine coefficients
// ---------------------------------------------------------------------------
__global__ void __launch_bounds__(256) ln_stats_kernel(
    const float* __restrict__ x,
    const float* __restrict__ norm_w,
    const float* __restrict__ norm_b,
    float* __restrict__ na, float* __restrict__ nb)
{
    const int bc = blockIdx.x;
    const float4* xp = (const float4*)(x + (size_t)bc * HWSZ);
    float s = 0.f, q = 0.f;
    for (int i = threadIdx.x; i < HWSZ / 4; i += 256) {
        float4 v = xp[i];
        s += v.x + v.y + v.z + v.w;
        q += v.x * v.x + v.y * v.y + v.z * v.z + v.w * v.w;
    }
    __shared__ float rs[256], rq[256];
    rs[threadIdx.x] = s; rq[threadIdx.x] = q;
    __syncthreads();
    for (int st = 128; st > 0; st >>= 1) {
        if (threadIdx.x < st) {
            rs[threadIdx.x] += rs[threadIdx.x + st];
            rq[threadIdx.x] += rq[threadIdx.x + st];
        }
        __syncthreads();
    }
    if (threadIdx.x == 0) {
        const float inv_n = 1.f / (float)HWSZ;
        float mean = rs[0] * inv_n;
        float var  = rq[0] * inv_n - mean * mean;
        int c = bc & (CCH - 1);
        float a = norm_w[c] * rsqrtf(var + EPSLN);
        na[bc] = a;
        nb[bc] = norm_b[c] - mean * a;
    }
}

// ---------------------------------------------------------------------------
// fp16 GEMM: Y[b,o,pos] = sum_c W[o,c]*X[b,c,pos] + bias[o]
// CTA: NT*128 o x 128 pos. W chunks of 64 cols via cp.async (wait_group 1).
// ---------------------------------------------------------------------------
#define GP 136
#define SW_OFF 0u
#define SX_OFF 34816u
#define SM_TOTAL 69632u

__device__ __forceinline__ void issue_chunk_f16(uint32_t sb,
    const __half* Wt, int c, int tid)
{
    #pragma unroll
    for (int rep = 0; rep < 4; rep++) {
        int s = tid + rep * 256;
        int o = s >> 3, col = c * 64 + (s & 7) * 8;
        CP_ASYNC16(sb + SW_OFF + (uint32_t)(o * GP + col) * 2u, Wt + o * CCH + col);
    }
    CP_COMMIT();
}

template<int NT, bool NORM, bool INF16, bool OUTF16>
__global__ void __launch_bounds__(256, 2) gemm_f16_kernel(
    const void* __restrict__ Xv,
    const __half* __restrict__ Wf,
    const float* __restrict__ bias,
    void* __restrict__ Yv,
    const float* __restrict__ na, const float* __restrict__ nb)
{
    extern __shared__ char smem[];
    const uint32_t sb = smem_u32(smem);
    const int tid  = threadIdx.x;
    const int wid  = tid >> 5;
    const int lane = tid & 31;
    const int wm   = wid & 3;
    const int wn   = wid >> 2;
    const int b    = blockIdx.y;
    const int pos0 = blockIdx.x * 128;

    issue_chunk_f16(sb, Wf, 0, tid);
    issue_chunk_f16(sb, Wf, 1, tid);

    // --- X staging: [c][pos] fp16 tile ---
    if (INF16) {
        const __half* Xh = (const __half*)Xv + (size_t)b * CCH * HWSZ + pos0;
        for (int i = tid; i < 128 * 16; i += 256) {
            int c = i >> 4, p8 = (i & 15) * 8;
            *(uint4*)(smem + SX_OFF + (uint32_t)(c * GP + p8) * 2u) =
                *(const uint4*)(Xh + (size_t)c * HWSZ + p8);
        }
    } else {
        const float* Xf = (const float*)Xv + (size_t)b * CCH * HWSZ + pos0;
        for (int i = tid; i < 128 * 32; i += 256) {
            int c = i >> 5, p4 = (i & 31) * 4;
            float4 v = *(const float4*)(Xf + (size_t)c * HWSZ + p4);
            if (NORM) {
                float a = na[b * CCH + c], bb = nb[b * CCH + c];
                v.x = fmaf(a, v.x, bb); v.y = fmaf(a, v.y, bb);
                v.z = fmaf(a, v.z, bb); v.w = fmaf(a, v.w, bb);
            }
            uint32_t off = SX_OFF + (uint32_t)(c * GP + p4) * 2u;
            *(uint2*)(smem + off) = make_uint2(
                h2u(__floats2half2_rn(v.x, v.y)), h2u(__floats2half2_rn(v.z, v.w)));
        }
    }
    __syncthreads();

    const uint32_t aaddr = sb + SW_OFF +
        (uint32_t)((wm * 32 + (lane & 15)) * GP + (lane >> 4) * 8) * 2u;
    const uint32_t baddr = sb + SX_OFF +
        (uint32_t)((lane & 15) * GP + wn * 64 + ((lane >> 4) & 1) * 8) * 2u;

    for (int ot = 0; ot < NT; ot++) {
        float acc[2][8][4];
        #pragma unroll
        for (int mi = 0; mi < 2; mi++)
            #pragma unroll
            for (int nf = 0; nf < 8; nf++)
                #pragma unroll
                for (int e = 0; e < 4; e++) acc[mi][nf][e] = 0.f;

        #pragma unroll
        for (int c = 0; c < 2; c++) {
            CP_WAIT1();
            __syncthreads();
            #pragma unroll
            for (int kk = 0; kk < 4; kk++) {
                const int ks = 4 * c + kk;
                uint32_t a0[4], a1[4];
                LDSM4(a0, aaddr + ks * 32);
                LDSM4(a1, aaddr + 16 * GP * 2 + ks * 32);
                #pragma unroll
                for (int g = 0; g < 4; g++) {
                    uint32_t bg[4];
                    LDSM4T(bg, baddr + ks * 16 * GP * 2 + g * 32);
                    MMAF16(acc[0][2 * g],     a0, bg[0], bg[1]);
                    MMAF16(acc[0][2 * g + 1], a0, bg[2], bg[3]);
                    MMAF16(acc[1][2 * g],     a1, bg[0], bg[1]);
                    MMAF16(acc[1][2 * g + 1], a1, bg[2], bg[3]);
                }
            }
            __syncthreads();
            if (ot + 1 < NT)
                issue_chunk_f16(sb, Wf + (size_t)(ot + 1) * 128 * CCH, c, tid);
            else
                CP_COMMIT();
        }

        // Epilogue
        #pragma unroll
        for (int mi = 0; mi < 2; mi++) {
            int r = ot * 128 + wm * 32 + mi * 16 + (lane >> 2);
            float bv0 = bias[r], bv1 = bias[r + 8];
            size_t rowoff = ((size_t)b * (NT * 128) + r) * HWSZ
                            + pos0 + wn * 64 + (lane & 3) * 2;
            if (OUTF16) {
                __half* Y0 = (__half*)Yv + rowoff;
                #pragma unroll
                for (int nf = 0; nf < 8; nf++) {
                    *(uint32_t*)(Y0 + nf * 8) = h2u(
                        __floats2half2_rn(acc[mi][nf][0] + bv0, acc[mi][nf][1] + bv0));
                    *(uint32_t*)(Y0 + (size_t)8 * HWSZ + nf * 8) = h2u(
                        __floats2half2_rn(acc[mi][nf][2] + bv1, acc[mi][nf][3] + bv1));
                }
            } else {
                float* Y0 = (float*)Yv + rowoff;
                #pragma unroll
                for (int nf = 0; nf < 8; nf++) {
                    *(float2*)(Y0 + nf * 8) =
                        make_float2(acc[mi][nf][0] + bv0, acc[mi][nf][1] + bv0);
                    *(float2*)(Y0 + (size_t)8 * HWSZ + nf * 8) =
                        make_float2(acc[mi][nf][2] + bv1, acc[mi][nf][3] + bv1);
                }
            }
        }
    }
}

// ---------------------------------------------------------------------------
// Kernel 3: attention, fp16, TWO adjacent windows per block (full 32B sectors).
// 256 thr / 8 warps; warp w: window w>>2, q-rows ((w&3)*16). Tiles [d][t] with
// t = win*64 + hh*8 + ww, pitch 136.
// ---------------------------------------------------------------------------
#define AP 136

__global__ void __launch_bounds__(256) attn_f16_kernel(
    const __half* __restrict__ qkv,
    __half* __restrict__ attn_out)
{
    __shared__ __align__(16) __half sQ[32 * AP];
    __shared__ __align__(16) __half sK[32 * AP];
    __shared__ __align__(16) __half sV[32 * AP];
    __shared__ __align__(16) __half OUT[32 * AP];

    const int bidx = blockIdx.x;
    const int head = bidx & 3;
    const int nwp  = (bidx >> 2) & 15;    // window-pair column
    const int nh   = (bidx >> 6) & 31;
    const int b    = bidx >> 11;
    const int tid  = threadIdx.x;
    const int wid  = tid >> 5;
    const int lane = tid & 31;
    const int win  = wid >> 2;            // 0 or 1
    const int wq   = wid & 3;             // q-row group within window

    const size_t base = ((size_t)b * (3 * CCH) + head * DIMH) * HWSZ;
    const int sp0 = (nh * WS) * WW + nwp * 16;
    const float scale = 0.1767766952966369f;

    // --- Load: thread = (d, tr); 32B row covers 8 t of each of 2 windows ---
    {
        int d = tid >> 3, tr = tid & 7;
        size_t g = base + (size_t)d * HWSZ + sp0 + tr * WW;
        int so = d * AP + tr * 8;
        const uint4* q0 = (const uint4*)(qkv + g);
        const uint4* k0 = (const uint4*)(qkv + g + (size_t)CCH * HWSZ);
        const uint4* v0 = (const uint4*)(qkv + g + (size_t)(2 * CCH) * HWSZ);
        *(uint4*)(sQ + so)      = q0[0];
        *(uint4*)(sQ + so + 64) = q0[1];
        *(uint4*)(sK + so)      = k0[0];
        *(uint4*)(sK + so + 64) = k0[1];
        *(uint4*)(sV + so)      = v0[0];
        *(uint4*)(sV + so + 64) = v0[1];
    }
    __syncthreads();

    const int W0 = win * 64;

    // --- QK^T: warp owns q rows [wq*16, wq*16+16) of its window ---
    const uint32_t aA = smem_u32(sQ) +
        (uint32_t)(((lane & 7) + (lane >> 4) * 8) * AP
                   + W0 + wq * 16 + ((lane >> 3) & 1) * 8) * 2u;
    const uint32_t bA = smem_u32(sK) +
        (uint32_t)(((lane & 7) + ((lane >> 3) & 1) * 8) * AP
                   + W0 + (lane >> 4) * 8) * 2u;

    float qacc[8][4];
    #pragma unroll
    for (int nf = 0; nf < 8; nf++)
        #pragma unroll
        for (int e = 0; e < 4; e++) qacc[nf][e] = 0.f;

    #pragma unroll
    for (int ks = 0; ks < 2; ks++) {
        uint32_t a[4];
        LDSM4T(a, aA + ks * 16 * AP * 2);
        #pragma unroll
        for (int sg = 0; sg < 4; sg++) {
            uint32_t bb[4];
            LDSM4T(bb, bA + sg * 32 + ks * 16 * AP * 2);
            MMAF16(qacc[2 * sg],     a, bb[0], bb[1]);
            MMAF16(qacc[2 * sg + 1], a, bb[2], bb[3]);
        }
    }

    // --- Softmax in registers (scale folded post-max) ---
    float mx0 = -1e30f, mx1 = -1e30f;
    #pragma unroll
    for (int nf = 0; nf < 8; nf++) {
        mx0 = fmaxf(mx0, fmaxf(qacc[nf][0], qacc[nf][1]));
        mx1 = fmaxf(mx1, fmaxf(qacc[nf][2], qacc[nf][3]));
    }
    mx0 = fmaxf(mx0, __shfl_xor_sync(0xFFFFFFFFu, mx0, 1));
    mx0 = fmaxf(mx0, __shfl_xor_sync(0xFFFFFFFFu, mx0, 2));
    mx1 = fmaxf(mx1, __shfl_xor_sync(0xFFFFFFFFu, mx1, 1));
    mx1 = fmaxf(mx1, __shfl_xor_sync(0xFFFFFFFFu, mx1, 2));

    float sm0 = 0.f, sm1 = 0.f;
    #pragma unroll
    for (int nf = 0; nf < 8; nf++) {
        qacc[nf][0] = __expf((qacc[nf][0] - mx0) * scale);
        qacc[nf][1] = __expf((qacc[nf][1] - mx0) * scale);
        qacc[nf][2] = __expf((qacc[nf][2] - mx1) * scale);
        qacc[nf][3] = __expf((qacc[nf][3] - mx1) * scale);
        sm0 += qacc[nf][0] + qacc[nf][1];
        sm1 += qacc[nf][2] + qacc[nf][3];
    }
    sm0 += __shfl_xor_sync(0xFFFFFFFFu, sm0, 1);
    sm0 += __shfl_xor_sync(0xFFFFFFFFu, sm0, 2);
    sm1 += __shfl_xor_sync(0xFFFFFFFFu, sm1, 1);
    sm1 += __shfl_xor_sync(0xFFFFFFFFu, sm1, 2);
    const float inv0 = 1.f / sm0, inv1 = 1.f / sm1;

    // --- P -> fp16 A-frags ---
    uint32_t pa[4][4];
    #pragma unroll
    for (int ks = 0; ks < 4; ks++) {
        int nf0 = 2 * ks, nf1 = nf0 + 1;
        pa[ks][0] = h2u(__floats2half2_rn(qacc[nf0][0] * inv0, qacc[nf0][1] * inv0));
        pa[ks][1] = h2u(__floats2half2_rn(qacc[nf0][2] * inv1, qacc[nf0][3] * inv1));
        pa[ks][2] = h2u(__floats2half2_rn(qacc[nf1][0] * inv0, qacc[nf1][1] * inv0));
        pa[ks][3] = h2u(__floats2half2_rn(qacc[nf1][2] * inv1, qacc[nf1][3] * inv1));
    }

    // --- PV: out[16 t][32 d] ---
    float oacc[4][4];
    #pragma unroll
    for (int nf = 0; nf < 4; nf++)
        #pragma unroll
        for (int e = 0; e < 4; e++) oacc[nf][e] = 0.f;

    const uint32_t vA = smem_u32(sV) +
        (uint32_t)((lane & 15) * AP + W0 + (lane >> 4) * 8) * 2u;
    #pragma unroll
    for (int ks = 0; ks < 4; ks++) {
        #pragma unroll
        for (int ng = 0; ng < 2; ng++) {
            uint32_t vh[4];
            LDSM4(vh, vA + ng * 16 * AP * 2 + ks * 32);
            MMAF16(oacc[2 * ng],     pa[ks], vh[0], vh[2]);
            MMAF16(oacc[2 * ng + 1], pa[ks], vh[1], vh[3]);
        }
    }

    // --- Stage fp16 [d][t] (separate buffer), then 32B coalesced writeback ---
    {
        int r = lane >> 2, cb = (lane & 3) * 2;
        int t = W0 + wq * 16 + r;
        #pragma unroll
        for (int nf = 0; nf < 4; nf++) {
            int d = nf * 8 + cb;
            OUT[d * AP + t]           = __float2half_rn(oacc[nf][0]);
            OUT[(d + 1) * AP + t]     = __float2half_rn(oacc[nf][1]);
            OUT[d * AP + t + 8]       = __float2half_rn(oacc[nf][2]);
            OUT[(d + 1) * AP + t + 8] = __float2half_rn(oacc[nf][3]);
        }
    }
    __syncthreads();

    const size_t obase = ((size_t)b * CCH + head * DIMH) * HWSZ;
    {
        int d = tid >> 3, tr = tid & 7;
        __half* gp = attn_out + obase + (size_t)d * HWSZ + sp0 + tr * WW;
        int so = d * AP + tr * 8;
        *(uint4*)(gp)     = *(const uint4*)(OUT + so);
        *(uint4*)(gp + 8) = *(const uint4*)(OUT + so + 64);
    }
}

// ---------------------------------------------------------------------------
// Launch
// ---------------------------------------------------------------------------
extern "C" void kernel_launch(void* const* d_in, const int* in_sizes, int n_in,
                              void* d_out, int out_size)
{
    const float* x      = (const float*)d_in[0];
    const float* norm_w = (const float*)d_in[1];
    const float* norm_b = (const float*)d_in[2];
    const float* qkv_w  = (const float*)d_in[3];
    const float* qkv_b  = (const float*)d_in[4];
    const float* proj_w = (const float*)d_in[5];
    const float* proj_b = (const float*)d_in[6];
    float* out = (float*)d_out;

    float *na, *nb;
    __half *qkvh, *attnh, *wf;
    cudaGetSymbolAddress((void**)&na,    g_na);
    cudaGetSymbolAddress((void**)&nb,    g_nb);
    cudaGetSymbolAddress((void**)&qkvh,  g_qkvh);
    cudaGetSymbolAddress((void**)&attnh, g_attnh);
    cudaGetSymbolAddress((void**)&wf,    g_wf);

    cudaFuncSetAttribute((const void*)gemm_f16_kernel<3, true, false, true>,
                         cudaFuncAttributeMaxDynamicSharedMemorySize, SM_TOTAL);
    cudaFuncSetAttribute((const void*)gemm_f16_kernel<1, false, true, false>,
                         cudaFuncAttributeMaxDynamicSharedMemorySize, SM_TOTAL);

    // 0) Weight convert (tiny)
    wconv_kernel<<<(4 * CCH * CCH + 255) / 256, 256>>>(qkv_w, proj_w, wf);

    // 1) LayerNorm stats
    ln_stats_kernel<<<BATCH * CCH, 256>>>(x, norm_w, norm_b, na, nb);

    // 2) QKV GEMM: fp32 in (LN fused), fp16 out
    gemm_f16_kernel<3, true, false, true><<<dim3(HWSZ / 128, BATCH), 256, SM_TOTAL>>>(
        x, wf, qkv_b, qkvh, na, nb);

    // 3) Window attention (fp16, 2 windows/block)
    attn_f16_kernel<<<BATCH * NWIN * (NWIN / 2) * HEADS, 256>>>(qkvh, attnh);

    // 4) Projection GEMM: fp16 in, fp32 out
    gemm_f16_kernel<1, false, true, false><<<dim3(HWSZ / 128, BATCH), 256, SM_TOTAL>>>(
        attnh, wf + 3 * CCH * CCH, proj_b, out, nullptr, nullptr);
}

// round 9
// speedup vs baseline: 5.9271x; 1.4524x over previous
#include <cuda_runtime.h>
#include <cuda_fp16.h>
#include <cstdint>

// Problem constants
#define BATCH 8
#define CCH   128
#define HH    256
#define WW    256
#define HWSZ  65536
#define HEADS 4
#define DIMH  32
#define WS    8
#define NWIN  32
#define EPSLN 1e-6f

// Scratch (device globals; allocation is forbidden)
__device__ float g_na[BATCH * CCH];
__device__ float g_nb[BATCH * CCH];
__device__ __half g_wf[(3 + 1) * CCH * CCH];   // qkv_w rows 0..383, proj_w rows 384..511

// ---------------------------------------------------------------------------
// Helpers (base-PTX features only: legal for compute_103)
// ---------------------------------------------------------------------------
__device__ __forceinline__ uint32_t smem_u32(const void* p) {
    uint32_t a;
    asm("{ .reg .u64 t; cvta.to.shared.u64 t, %1; cvt.u32.u64 %0, t; }" : "=r"(a) : "l"(p));
    return a;
}

#define LDSM4(r, addr) \
    asm volatile("ldmatrix.sync.aligned.m8n8.x4.shared.b16 {%0,%1,%2,%3}, [%4];" \
        : "=r"((r)[0]), "=r"((r)[1]), "=r"((r)[2]), "=r"((r)[3]) : "r"(addr))

#define LDSM4T(r, addr) \
    asm volatile("ldmatrix.sync.aligned.m8n8.x4.trans.shared.b16 {%0,%1,%2,%3}, [%4];" \
        : "=r"((r)[0]), "=r"((r)[1]), "=r"((r)[2]), "=r"((r)[3]) : "r"(addr))

#define MMAF16(d, a, b0, b1) \
    asm volatile("mma.sync.aligned.m16n8k16.row.col.f32.f16.f16.f32 " \
        "{%0,%1,%2,%3}, {%4,%5,%6,%7}, {%8,%9}, {%0,%1,%2,%3};" \
        : "+f"((d)[0]), "+f"((d)[1]), "+f"((d)[2]), "+f"((d)[3]) \
        : "r"((a)[0]), "r"((a)[1]), "r"((a)[2]), "r"((a)[3]), "r"(b0), "r"(b1))

#define CP_ASYNC16(dst, src) \
    asm volatile("cp.async.cg.shared.global [%0], [%1], 16;" :: "r"(dst), "l"(src))
#define CP_COMMIT() asm volatile("cp.async.commit_group;" ::: "memory")
#define CP_WAIT1()  asm volatile("cp.async.wait_group 1;" ::: "memory")
#define CP_WAIT0()  asm volatile("cp.async.wait_group 0;" ::: "memory")

__device__ __forceinline__ uint32_t h2u(__half2 h) {
    uint32_t u;
    *(__half2*)&u = h;
    return u;
}

// ---------------------------------------------------------------------------
// Kernel 0: convert weights to fp16
// ---------------------------------------------------------------------------
__global__ void wconv_kernel(const float* __restrict__ qkv_w,
                             const float* __restrict__ proj_w,
                             __half* __restrict__ wf)
{
    int i = blockIdx.x * 256 + threadIdx.x;
    const int nq = 3 * CCH * CCH;
    const int nt = 4 * CCH * CCH;
    if (i < nt)
        wf[i] = __float2half_rn((i < nq) ? qkv_w[i] : proj_w[i - nq]);
}

// ---------------------------------------------------------------------------
// Kernel 1: LayerNorm2d stats -> per-(b,c) affine coefficients
// ---------------------------------------------------------------------------
__global__ void __launch_bounds__(256) ln_stats_kernel(
    const float* __restrict__ x,
    const float* __restrict__ norm_w,
    const float* __restrict__ norm_b,
    float* __restrict__ na, float* __restrict__ nb)
{
    const int bc = blockIdx.x;
    const float4* xp = (const float4*)(x + (size_t)bc * HWSZ);
    float s = 0.f, q = 0.f;
    for (int i = threadIdx.x; i < HWSZ / 4; i += 256) {
        float4 v = xp[i];
        s += v.x + v.y + v.z + v.w;
        q += v.x * v.x + v.y * v.y + v.z * v.z + v.w * v.w;
    }
    __shared__ float rs[256], rq[256];
    rs[threadIdx.x] = s; rq[threadIdx.x] = q;
    __syncthreads();
    for (int st = 128; st > 0; st >>= 1) {
        if (threadIdx.x < st) {
            rs[threadIdx.x] += rs[threadIdx.x + st];
            rq[threadIdx.x] += rq[threadIdx.x + st];
        }
        __syncthreads();
    }
    if (threadIdx.x == 0) {
        const float inv_n = 1.f / (float)HWSZ;
        float mean = rs[0] * inv_n;
        float var  = rq[0] * inv_n - mean * mean;
        int c = bc & (CCH - 1);
        float a = norm_w[c] * rsqrtf(var + EPSLN);
        na[bc] = a;
        nb[bc] = norm_b[c] - mean * a;
    }
}

// ---------------------------------------------------------------------------
// Fused kernel: one block = one (b, nh, window-pair). 256 thr / 8 warps.
// Tile columns: pos j = r*16 + c16 (r = image row 0..7, c16 = col within
// 16-wide pair strip). Window t -> tile col: tcol(t) = (t>>3)*16 + win*8 + (t&7).
// Phases: X load (LN fused) -> QKV GEMM (3 tiles) -> attention -> proj GEMM.
// smem: sX [128][136] | W slot0 | W slot1 | sQKV 3x[128][136]  = 204 KB.
// ---------------------------------------------------------------------------
#define TP 136
#define SX_B   0u
#define SW0_B  34816u
#define SW1_B  69632u
#define SQ_B   104448u          // q tile; k at +34816, v at +69632
#define FUSED_SMEM 208896u

__device__ __forceinline__ void issue_wtile(uint32_t slot, const __half* Wt, int tid) {
    #pragma unroll
    for (int rep = 0; rep < 8; rep++) {
        int s = tid + rep * 256;
        int o = s >> 4, c8 = (s & 15) * 8;
        CP_ASYNC16(slot + (uint32_t)(o * TP + c8) * 2u, Wt + o * CCH + c8);
    }
    CP_COMMIT();
}

__global__ void fused_kernel(
    const float* __restrict__ x,
    const __half* __restrict__ wf,
    const float* __restrict__ qkv_b,
    const float* __restrict__ proj_b,
    float* __restrict__ out,
    const float* __restrict__ na, const float* __restrict__ nb)
{
    extern __shared__ char smem[];
    const uint32_t sb = smem_u32(smem);
    const int tid  = threadIdx.x;
    const int wid  = tid >> 5;
    const int lane = tid & 31;
    const int wm   = wid & 3;
    const int wn   = wid >> 2;
    const int nwp  = blockIdx.x;           // window-pair column (0..15)
    const int nh   = blockIdx.y;           // window row (0..31)
    const int b    = blockIdx.z;
    const int sp0  = (nh * WS) * WW + nwp * 16;

    // Prefetch W tiles 0,1
    issue_wtile(sb + SW0_B, wf, tid);
    issue_wtile(sb + SW1_B, wf + 128 * CCH, tid);

    // --- Phase 1: X load, LN affine, fp16, tile-col order ---
    {
        const float* Xb = x + (size_t)b * CCH * HWSZ + sp0;
        #pragma unroll
        for (int rep = 0; rep < 16; rep++) {
            int s = tid + rep * 256;
            int c = s >> 5, j4 = (s & 31) * 4;
            float4 v = *(const float4*)(Xb + (size_t)c * HWSZ + (j4 >> 4) * WW + (j4 & 15));
            float a = na[b * CCH + c], bb = nb[b * CCH + c];
            v.x = fmaf(a, v.x, bb); v.y = fmaf(a, v.y, bb);
            v.z = fmaf(a, v.z, bb); v.w = fmaf(a, v.w, bb);
            *(uint2*)(smem + SX_B + (uint32_t)(c * TP + j4) * 2u) = make_uint2(
                h2u(__floats2half2_rn(v.x, v.y)), h2u(__floats2half2_rn(v.z, v.w)));
        }
    }

    // Fragment base addresses (B operand from sX / sATT: same formula)
    const uint32_t baddr = sb + SX_B +
        (uint32_t)((lane & 15) * TP + wn * 64 + ((lane >> 4) & 1) * 8) * 2u;
    const uint32_t aoff =
        (uint32_t)((wm * 32 + (lane & 15)) * TP + (lane >> 4) * 8) * 2u;

    // --- Phase 2: QKV GEMM, 3 output tiles ---
    for (int wt = 0; wt < 3; wt++) {
        CP_WAIT1();
        __syncthreads();
        const uint32_t aaddr = sb + ((wt & 1) ? SW1_B : SW0_B) + aoff;

        float acc[2][8][4];
        #pragma unroll
        for (int mi = 0; mi < 2; mi++)
            #pragma unroll
            for (int nf = 0; nf < 8; nf++)
                #pragma unroll
                for (int e = 0; e < 4; e++) acc[mi][nf][e] = 0.f;

        #pragma unroll
        for (int ks = 0; ks < 8; ks++) {
            uint32_t a0[4], a1[4];
            LDSM4(a0, aaddr + ks * 32);
            LDSM4(a1, aaddr + 16 * TP * 2 + ks * 32);
            #pragma unroll
            for (int g = 0; g < 4; g++) {
                uint32_t bg[4];
                LDSM4T(bg, baddr + ks * 16 * TP * 2 + g * 32);
                MMAF16(acc[0][2 * g],     a0, bg[0], bg[1]);
                MMAF16(acc[0][2 * g + 1], a0, bg[2], bg[3]);
                MMAF16(acc[1][2 * g],     a1, bg[0], bg[1]);
                MMAF16(acc[1][2 * g + 1], a1, bg[2], bg[3]);
            }
        }

        // Epilogue -> sQKV[wt] fp16 (+bias)
        const uint32_t qb = sb + SQ_B + (uint32_t)wt * 34816u;
        #pragma unroll
        for (int mi = 0; mi < 2; mi++) {
            int r = wm * 32 + mi * 16 + (lane >> 2);
            float bv0 = qkv_b[wt * 128 + r], bv1 = qkv_b[wt * 128 + r + 8];
            #pragma unroll
            for (int nf = 0; nf < 8; nf++) {
                int col = wn * 64 + nf * 8 + (lane & 3) * 2;
                *(uint32_t*)(smem + (qb - sb) + (uint32_t)(r * TP + col) * 2u) = h2u(
                    __floats2half2_rn(acc[mi][nf][0] + bv0, acc[mi][nf][1] + bv0));
                *(uint32_t*)(smem + (qb - sb) + (uint32_t)((r + 8) * TP + col) * 2u) = h2u(
                    __floats2half2_rn(acc[mi][nf][2] + bv1, acc[mi][nf][3] + bv1));
            }
        }
        __syncthreads();
        if (wt == 0) issue_wtile(sb + SW0_B, wf + 2 * 128 * CCH, tid);  // W2
        if (wt == 1) issue_wtile(sb + SW1_B, wf + 3 * 128 * CCH, tid);  // Wproj
    }

    // --- Phase 3: attention. warp = (win, wq); loop over 4 heads ---
    {
        const int win = wid >> 2;
        const int wq  = wid & 3;
        const int W8  = win * 8;
        const float scale = 0.1767766952966369f;
        const uint32_t sQt = sb + SQ_B;
        const uint32_t sKt = sQt + 34816u;
        const uint32_t sVt = sQt + 69632u;

        for (int h = 0; h < 4; h++) {
            const int hr = h * 32;
            const uint32_t aA = sQt +
                (uint32_t)((hr + (lane & 7) + (lane >> 4) * 8) * TP
                           + wq * 32 + ((lane >> 3) & 1) * 16 + W8) * 2u;
            const uint32_t bA = sKt +
                (uint32_t)((hr + (lane & 7) + ((lane >> 3) & 1) * 8) * TP
                           + (lane >> 4) * 16 + W8) * 2u;

            float qacc[8][4];
            #pragma unroll
            for (int nf = 0; nf < 8; nf++)
                #pragma unroll
                for (int e = 0; e < 4; e++) qacc[nf][e] = 0.f;

            #pragma unroll
            for (int ks = 0; ks < 2; ks++) {
                uint32_t a[4];
                LDSM4T(a, aA + ks * 16 * TP * 2);
                #pragma unroll
                for (int sg = 0; sg < 4; sg++) {
                    uint32_t bb[4];
                    LDSM4T(bb, bA + sg * 64 + ks * 16 * TP * 2);
                    MMAF16(qacc[2 * sg],     a, bb[0], bb[1]);
                    MMAF16(qacc[2 * sg + 1], a, bb[2], bb[3]);
                }
            }

            // Softmax (scale folded post-max)
            float mx0 = -1e30f, mx1 = -1e30f;
            #pragma unroll
            for (int nf = 0; nf < 8; nf++) {
                mx0 = fmaxf(mx0, fmaxf(qacc[nf][0], qacc[nf][1]));
                mx1 = fmaxf(mx1, fmaxf(qacc[nf][2], qacc[nf][3]));
            }
            mx0 = fmaxf(mx0, __shfl_xor_sync(0xFFFFFFFFu, mx0, 1));
            mx0 = fmaxf(mx0, __shfl_xor_sync(0xFFFFFFFFu, mx0, 2));
            mx1 = fmaxf(mx1, __shfl_xor_sync(0xFFFFFFFFu, mx1, 1));
            mx1 = fmaxf(mx1, __shfl_xor_sync(0xFFFFFFFFu, mx1, 2));

            float sm0 = 0.f, sm1 = 0.f;
            #pragma unroll
            for (int nf = 0; nf < 8; nf++) {
                qacc[nf][0] = __expf((qacc[nf][0] - mx0) * scale);
                qacc[nf][1] = __expf((qacc[nf][1] - mx0) * scale);
                qacc[nf][2] = __expf((qacc[nf][2] - mx1) * scale);
                qacc[nf][3] = __expf((qacc[nf][3] - mx1) * scale);
                sm0 += qacc[nf][0] + qacc[nf][1];
                sm1 += qacc[nf][2] + qacc[nf][3];
            }
            sm0 += __shfl_xor_sync(0xFFFFFFFFu, sm0, 1);
            sm0 += __shfl_xor_sync(0xFFFFFFFFu, sm0, 2);
            sm1 += __shfl_xor_sync(0xFFFFFFFFu, sm1, 1);
            sm1 += __shfl_xor_sync(0xFFFFFFFFu, sm1, 2);
            const float inv0 = 1.f / sm0, inv1 = 1.f / sm1;

            uint32_t pa[4][4];
            #pragma unroll
            for (int ks = 0; ks < 4; ks++) {
                int nf0 = 2 * ks, nf1 = nf0 + 1;
                pa[ks][0] = h2u(__floats2half2_rn(qacc[nf0][0] * inv0, qacc[nf0][1] * inv0));
                pa[ks][1] = h2u(__floats2half2_rn(qacc[nf0][2] * inv1, qacc[nf0][3] * inv1));
                pa[ks][2] = h2u(__floats2half2_rn(qacc[nf1][0] * inv0, qacc[nf1][1] * inv0));
                pa[ks][3] = h2u(__floats2half2_rn(qacc[nf1][2] * inv1, qacc[nf1][3] * inv1));
            }

            float oacc[4][4];
            #pragma unroll
            for (int nf = 0; nf < 4; nf++)
                #pragma unroll
                for (int e = 0; e < 4; e++) oacc[nf][e] = 0.f;

            const uint32_t vA = sVt +
                (uint32_t)((hr + (lane & 15)) * TP + (lane >> 4) * 16 + W8) * 2u;
            #pragma unroll
            for (int ks = 0; ks < 4; ks++) {
                #pragma unroll
                for (int ng = 0; ng < 2; ng++) {
                    uint32_t vh[4];
                    LDSM4(vh, vA + ng * 16 * TP * 2 + ks * 64);
                    MMAF16(oacc[2 * ng],     pa[ks], vh[0], vh[2]);
                    MMAF16(oacc[2 * ng + 1], pa[ks], vh[1], vh[3]);
                }
            }

            // Store to sATT (reuses sX region; X dead after phase 2)
            {
                int r = lane >> 2, cb = (lane & 3) * 2;
                int col = wq * 32 + W8 + r;
                __half* ATT = (__half*)(smem + SX_B);
                #pragma unroll
                for (int nf = 0; nf < 4; nf++) {
                    int d = hr + nf * 8 + cb;
                    ATT[d * TP + col]            = __float2half_rn(oacc[nf][0]);
                    ATT[(d + 1) * TP + col]      = __float2half_rn(oacc[nf][1]);
                    ATT[d * TP + col + 16]       = __float2half_rn(oacc[nf][2]);
                    ATT[(d + 1) * TP + col + 16] = __float2half_rn(oacc[nf][3]);
                }
            }
        }
    }
    CP_WAIT0();
    __syncthreads();   // sATT complete; Wproj landed

    // --- Phase 4: proj GEMM from sATT (same layout as sX) + Wproj (slot1) ---
    {
        const uint32_t aaddr = sb + SW1_B + aoff;
        float acc[2][8][4];
        #pragma unroll
        for (int mi = 0; mi < 2; mi++)
            #pragma unroll
            for (int nf = 0; nf < 8; nf++)
                #pragma unroll
                for (int e = 0; e < 4; e++) acc[mi][nf][e] = 0.f;

        #pragma unroll
        for (int ks = 0; ks < 8; ks++) {
            uint32_t a0[4], a1[4];
            LDSM4(a0, aaddr + ks * 32);
            LDSM4(a1, aaddr + 16 * TP * 2 + ks * 32);
            #pragma unroll
            for (int g = 0; g < 4; g++) {
                uint32_t bg[4];
                LDSM4T(bg, baddr + ks * 16 * TP * 2 + g * 32);
                MMAF16(acc[0][2 * g],     a0, bg[0], bg[1]);
                MMAF16(acc[0][2 * g + 1], a0, bg[2], bg[3]);
                MMAF16(acc[1][2 * g],     a1, bg[0], bg[1]);
                MMAF16(acc[1][2 * g + 1], a1, bg[2], bg[3]);
            }
        }

        // Epilogue: fp32 direct to gmem
        #pragma unroll
        for (int mi = 0; mi < 2; mi++) {
            int r = wm * 32 + mi * 16 + (lane >> 2);
            float bv0 = proj_b[r], bv1 = proj_b[r + 8];
            float* O0 = out + ((size_t)b * CCH + r) * HWSZ + sp0;
            #pragma unroll
            for (int nf = 0; nf < 8; nf++) {
                int col = wn * 64 + nf * 8 + (lane & 3) * 2;
                int gpos = (col >> 4) * WW + (col & 15);
                *(float2*)(O0 + gpos) =
                    make_float2(acc[mi][nf][0] + bv0, acc[mi][nf][1] + bv0);
                *(float2*)(O0 + (size_t)8 * HWSZ + gpos) =
                    make_float2(acc[mi][nf][2] + bv1, acc[mi][nf][3] + bv1);
            }
        }
    }
}

// ---------------------------------------------------------------------------
// Launch
// ---------------------------------------------------------------------------
extern "C" void kernel_launch(void* const* d_in, const int* in_sizes, int n_in,
                              void* d_out, int out_size)
{
    const float* x      = (const float*)d_in[0];
    const float* norm_w = (const float*)d_in[1];
    const float* norm_b = (const float*)d_in[2];
    const float* qkv_w  = (const float*)d_in[3];
    const float* qkv_b  = (const float*)d_in[4];
    const float* proj_w = (const float*)d_in[5];
    const float* proj_b = (const float*)d_in[6];
    float* out = (float*)d_out;

    float *na, *nb;
    __half *wf;
    cudaGetSymbolAddress((void**)&na, g_na);
    cudaGetSymbolAddress((void**)&nb, g_nb);
    cudaGetSymbolAddress((void**)&wf, g_wf);

    cudaFuncSetAttribute(fused_kernel,
                         cudaFuncAttributeMaxDynamicSharedMemorySize, FUSED_SMEM);

    // 0) Weight convert (tiny)
    wconv_kernel<<<(4 * CCH * CCH + 255) / 256, 256>>>(qkv_w, proj_w, wf);

    // 1) LayerNorm stats
    ln_stats_kernel<<<BATCH * CCH, 256>>>(x, norm_w, norm_b, na, nb);

    // 2) Fused LN-affine + QKV + attention + proj
    fused_kernel<<<dim3(NWIN / 2, NWIN, BATCH), 256, FUSED_SMEM>>>(
        x, wf, qkv_b, proj_b, out, na, nb);
}

// round 10
// speedup vs baseline: 6.1851x; 1.0435x over previous
#include <cuda_runtime.h>
#include <cuda_fp16.h>
#include <cstdint>

// Problem constants
#define BATCH 8
#define CCH   128
#define HH    256
#define WW    256
#define HWSZ  65536
#define HEADS 4
#define DIMH  32
#define WS    8
#define NWIN  32
#define EPSLN 1e-6f

// Scratch (device globals; allocation is forbidden)
__device__ float g_na[BATCH * CCH];
__device__ float g_nb[BATCH * CCH];
__device__ __half g_wf[(3 + 1) * CCH * CCH];   // qkv_w rows 0..383, proj_w rows 384..511

// ---------------------------------------------------------------------------
// Helpers (base-PTX features only: legal for compute_103)
// ---------------------------------------------------------------------------
__device__ __forceinline__ uint32_t smem_u32(const void* p) {
    uint32_t a;
    asm("{ .reg .u64 t; cvta.to.shared.u64 t, %1; cvt.u32.u64 %0, t; }" : "=r"(a) : "l"(p));
    return a;
}

#define LDSM4(r, addr) \
    asm volatile("ldmatrix.sync.aligned.m8n8.x4.shared.b16 {%0,%1,%2,%3}, [%4];" \
        : "=r"((r)[0]), "=r"((r)[1]), "=r"((r)[2]), "=r"((r)[3]) : "r"(addr))

#define LDSM4T(r, addr) \
    asm volatile("ldmatrix.sync.aligned.m8n8.x4.trans.shared.b16 {%0,%1,%2,%3}, [%4];" \
        : "=r"((r)[0]), "=r"((r)[1]), "=r"((r)[2]), "=r"((r)[3]) : "r"(addr))

#define MMAF16(d, a, b0, b1) \
    asm volatile("mma.sync.aligned.m16n8k16.row.col.f32.f16.f16.f32 " \
        "{%0,%1,%2,%3}, {%4,%5,%6,%7}, {%8,%9}, {%0,%1,%2,%3};" \
        : "+f"((d)[0]), "+f"((d)[1]), "+f"((d)[2]), "+f"((d)[3]) \
        : "r"((a)[0]), "r"((a)[1]), "r"((a)[2]), "r"((a)[3]), "r"(b0), "r"(b1))

#define CP_ASYNC16(dst, src) \
    asm volatile("cp.async.cg.shared.global [%0], [%1], 16;" :: "r"(dst), "l"(src))
#define CP_COMMIT() asm volatile("cp.async.commit_group;" ::: "memory")
#define CP_WAIT1()  asm volatile("cp.async.wait_group 1;" ::: "memory")
#define CP_WAIT0()  asm volatile("cp.async.wait_group 0;" ::: "memory")

__device__ __forceinline__ uint32_t h2u(__half2 h) {
    uint32_t u;
    *(__half2*)&u = h;
    return u;
}

// ---------------------------------------------------------------------------
// Kernel 0: convert weights to fp16
// ---------------------------------------------------------------------------
__global__ void wconv_kernel(const float* __restrict__ qkv_w,
                             const float* __restrict__ proj_w,
                             __half* __restrict__ wf)
{
    int i = blockIdx.x * 256 + threadIdx.x;
    const int nq = 3 * CCH * CCH;
    const int nt = 4 * CCH * CCH;
    if (i < nt)
        wf[i] = __float2half_rn((i < nq) ? qkv_w[i] : proj_w[i - nq]);
}

// ---------------------------------------------------------------------------
// Kernel 1: LayerNorm2d stats -> per-(b,c) affine coefficients
// ---------------------------------------------------------------------------
__global__ void __launch_bounds__(256) ln_stats_kernel(
    const float* __restrict__ x,
    const float* __restrict__ norm_w,
    const float* __restrict__ norm_b,
    float* __restrict__ na, float* __restrict__ nb)
{
    const int bc = blockIdx.x;
    const float4* xp = (const float4*)(x + (size_t)bc * HWSZ);
    float s = 0.f, q = 0.f;
    for (int i = threadIdx.x; i < HWSZ / 4; i += 256) {
        float4 v = xp[i];
        s += v.x + v.y + v.z + v.w;
        q += v.x * v.x + v.y * v.y + v.z * v.z + v.w * v.w;
    }
    __shared__ float rs[256], rq[256];
    rs[threadIdx.x] = s; rq[threadIdx.x] = q;
    __syncthreads();
    for (int st = 128; st > 0; st >>= 1) {
        if (threadIdx.x < st) {
            rs[threadIdx.x] += rs[threadIdx.x + st];
            rq[threadIdx.x] += rq[threadIdx.x + st];
        }
        __syncthreads();
    }
    if (threadIdx.x == 0) {
        const float inv_n = 1.f / (float)HWSZ;
        float mean = rs[0] * inv_n;
        float var  = rq[0] * inv_n - mean * mean;
        int c = bc & (CCH - 1);
        float a = norm_w[c] * rsqrtf(var + EPSLN);
        na[bc] = a;
        nb[bc] = norm_b[c] - mean * a;
    }
}

// ---------------------------------------------------------------------------
// Fused kernel v2: 512 threads / 16 warps, one (b, nh, window-pair) per block.
// GEMM phases: warp grid 4x4, tile 32o x 32pos. Attention: warp = (hh, win, wq),
// 2 heads per warp. smem layout identical to R9 (204 KB, 1 CTA/SM).
// ---------------------------------------------------------------------------
#define TP 136
#define SX_B   0u
#define SW0_B  34816u
#define SW1_B  69632u
#define SQ_B   104448u          // q tile; k at +34816, v at +69632
#define FUSED_SMEM 208896u

__device__ __forceinline__ void issue_wtile(uint32_t slot, const __half* Wt, int tid) {
    #pragma unroll
    for (int rep = 0; rep < 4; rep++) {
        int s = tid + rep * 512;
        int o = s >> 4, c8 = (s & 15) * 8;
        CP_ASYNC16(slot + (uint32_t)(o * TP + c8) * 2u, Wt + o * CCH + c8);
    }
    CP_COMMIT();
}

__global__ void __launch_bounds__(512) fused_kernel(
    const float* __restrict__ x,
    const __half* __restrict__ wf,
    const float* __restrict__ qkv_b,
    const float* __restrict__ proj_b,
    float* __restrict__ out,
    const float* __restrict__ na, const float* __restrict__ nb)
{
    extern __shared__ char smem[];
    const uint32_t sb = smem_u32(smem);
    const int tid  = threadIdx.x;
    const int wid  = tid >> 5;
    const int lane = tid & 31;
    const int wm   = wid & 3;
    const int wn   = wid >> 2;              // 0..3 -> 32-pos group
    const int nwp  = blockIdx.x;
    const int nh   = blockIdx.y;
    const int b    = blockIdx.z;
    const int sp0  = (nh * WS) * WW + nwp * 16;

    // Prefetch W tiles 0,1
    issue_wtile(sb + SW0_B, wf, tid);
    issue_wtile(sb + SW1_B, wf + 128 * CCH, tid);

    // --- Phase 1: X load, LN affine, fp16, tile-col order ---
    {
        const float* Xb = x + (size_t)b * CCH * HWSZ + sp0;
        #pragma unroll
        for (int rep = 0; rep < 8; rep++) {
            int s = tid + rep * 512;
            int c = s >> 5, j4 = (s & 31) * 4;
            float4 v = *(const float4*)(Xb + (size_t)c * HWSZ + (j4 >> 4) * WW + (j4 & 15));
            float a = na[b * CCH + c], bb = nb[b * CCH + c];
            v.x = fmaf(a, v.x, bb); v.y = fmaf(a, v.y, bb);
            v.z = fmaf(a, v.z, bb); v.w = fmaf(a, v.w, bb);
            *(uint2*)(smem + SX_B + (uint32_t)(c * TP + j4) * 2u) = make_uint2(
                h2u(__floats2half2_rn(v.x, v.y)), h2u(__floats2half2_rn(v.z, v.w)));
        }
    }

    // Fragment base addresses (B operand from sX / sATT: same formula)
    const uint32_t baddr = sb + SX_B +
        (uint32_t)((lane & 15) * TP + wn * 32 + ((lane >> 4) & 1) * 8) * 2u;
    const uint32_t aoff =
        (uint32_t)((wm * 32 + (lane & 15)) * TP + (lane >> 4) * 8) * 2u;

    // --- Phase 2: QKV GEMM, 3 output tiles, warp tile 32o x 32pos ---
    for (int wt = 0; wt < 3; wt++) {
        CP_WAIT1();
        __syncthreads();
        const uint32_t aaddr = sb + ((wt & 1) ? SW1_B : SW0_B) + aoff;

        float acc[2][4][4];
        #pragma unroll
        for (int mi = 0; mi < 2; mi++)
            #pragma unroll
            for (int nf = 0; nf < 4; nf++)
                #pragma unroll
                for (int e = 0; e < 4; e++) acc[mi][nf][e] = 0.f;

        #pragma unroll
        for (int ks = 0; ks < 8; ks++) {
            uint32_t a0[4], a1[4];
            LDSM4(a0, aaddr + ks * 32);
            LDSM4(a1, aaddr + 16 * TP * 2 + ks * 32);
            #pragma unroll
            for (int g = 0; g < 2; g++) {
                uint32_t bg[4];
                LDSM4T(bg, baddr + ks * 16 * TP * 2 + g * 32);
                MMAF16(acc[0][2 * g],     a0, bg[0], bg[1]);
                MMAF16(acc[0][2 * g + 1], a0, bg[2], bg[3]);
                MMAF16(acc[1][2 * g],     a1, bg[0], bg[1]);
                MMAF16(acc[1][2 * g + 1], a1, bg[2], bg[3]);
            }
        }

        // Epilogue -> sQKV[wt] fp16 (+bias)
        const uint32_t qoff = SQ_B + (uint32_t)wt * 34816u;
        #pragma unroll
        for (int mi = 0; mi < 2; mi++) {
            int r = wm * 32 + mi * 16 + (lane >> 2);
            float bv0 = qkv_b[wt * 128 + r], bv1 = qkv_b[wt * 128 + r + 8];
            #pragma unroll
            for (int nf = 0; nf < 4; nf++) {
                int col = wn * 32 + nf * 8 + (lane & 3) * 2;
                *(uint32_t*)(smem + qoff + (uint32_t)(r * TP + col) * 2u) = h2u(
                    __floats2half2_rn(acc[mi][nf][0] + bv0, acc[mi][nf][1] + bv0));
                *(uint32_t*)(smem + qoff + (uint32_t)((r + 8) * TP + col) * 2u) = h2u(
                    __floats2half2_rn(acc[mi][nf][2] + bv1, acc[mi][nf][3] + bv1));
            }
        }
        __syncthreads();
        if (wt == 0) issue_wtile(sb + SW0_B, wf + 2 * 128 * CCH, tid);  // W2
        if (wt == 1) issue_wtile(sb + SW1_B, wf + 3 * 128 * CCH, tid);  // Wproj
    }

    // --- Phase 3: attention. warp = (hh, win, wq); 2 heads per warp ---
    {
        const int hh  = wid >> 3;           // head pair 0/1
        const int win = (wid >> 2) & 1;
        const int wq  = wid & 3;
        const int W8  = win * 8;
        const float scale = 0.1767766952966369f;
        const uint32_t sQt = sb + SQ_B;
        const uint32_t sKt = sQt + 34816u;
        const uint32_t sVt = sQt + 69632u;

        #pragma unroll
        for (int hi = 0; hi < 2; hi++) {
            const int hr = (hh * 2 + hi) * 32;
            const uint32_t aA = sQt +
                (uint32_t)((hr + (lane & 7) + (lane >> 4) * 8) * TP
                           + wq * 32 + ((lane >> 3) & 1) * 16 + W8) * 2u;
            const uint32_t bA = sKt +
                (uint32_t)((hr + (lane & 7) + ((lane >> 3) & 1) * 8) * TP
                           + (lane >> 4) * 16 + W8) * 2u;

            float qacc[8][4];
            #pragma unroll
            for (int nf = 0; nf < 8; nf++)
                #pragma unroll
                for (int e = 0; e < 4; e++) qacc[nf][e] = 0.f;

            #pragma unroll
            for (int ks = 0; ks < 2; ks++) {
                uint32_t a[4];
                LDSM4T(a, aA + ks * 16 * TP * 2);
                #pragma unroll
                for (int sg = 0; sg < 4; sg++) {
                    uint32_t bb[4];
                    LDSM4T(bb, bA + sg * 64 + ks * 16 * TP * 2);
                    MMAF16(qacc[2 * sg],     a, bb[0], bb[1]);
                    MMAF16(qacc[2 * sg + 1], a, bb[2], bb[3]);
                }
            }

            // Softmax (scale folded post-max)
            float mx0 = -1e30f, mx1 = -1e30f;
            #pragma unroll
            for (int nf = 0; nf < 8; nf++) {
                mx0 = fmaxf(mx0, fmaxf(qacc[nf][0], qacc[nf][1]));
                mx1 = fmaxf(mx1, fmaxf(qacc[nf][2], qacc[nf][3]));
            }
            mx0 = fmaxf(mx0, __shfl_xor_sync(0xFFFFFFFFu, mx0, 1));
            mx0 = fmaxf(mx0, __shfl_xor_sync(0xFFFFFFFFu, mx0, 2));
            mx1 = fmaxf(mx1, __shfl_xor_sync(0xFFFFFFFFu, mx1, 1));
            mx1 = fmaxf(mx1, __shfl_xor_sync(0xFFFFFFFFu, mx1, 2));

            float sm0 = 0.f, sm1 = 0.f;
            #pragma unroll
            for (int nf = 0; nf < 8; nf++) {
                qacc[nf][0] = __expf((qacc[nf][0] - mx0) * scale);
                qacc[nf][1] = __expf((qacc[nf][1] - mx0) * scale);
                qacc[nf][2] = __expf((qacc[nf][2] - mx1) * scale);
                qacc[nf][3] = __expf((qacc[nf][3] - mx1) * scale);
                sm0 += qacc[nf][0] + qacc[nf][1];
                sm1 += qacc[nf][2] + qacc[nf][3];
            }
            sm0 += __shfl_xor_sync(0xFFFFFFFFu, sm0, 1);
            sm0 += __shfl_xor_sync(0xFFFFFFFFu, sm0, 2);
            sm1 += __shfl_xor_sync(0xFFFFFFFFu, sm1, 1);
            sm1 += __shfl_xor_sync(0xFFFFFFFFu, sm1, 2);
            const float inv0 = 1.f / sm0, inv1 = 1.f / sm1;

            uint32_t pa[4][4];
            #pragma unroll
            for (int ks = 0; ks < 4; ks++) {
                int nf0 = 2 * ks, nf1 = nf0 + 1;
                pa[ks][0] = h2u(__floats2half2_rn(qacc[nf0][0] * inv0, qacc[nf0][1] * inv0));
                pa[ks][1] = h2u(__floats2half2_rn(qacc[nf0][2] * inv1, qacc[nf0][3] * inv1));
                pa[ks][2] = h2u(__floats2half2_rn(qacc[nf1][0] * inv0, qacc[nf1][1] * inv0));
                pa[ks][3] = h2u(__floats2half2_rn(qacc[nf1][2] * inv1, qacc[nf1][3] * inv1));
            }

            float oacc[4][4];
            #pragma unroll
            for (int nf = 0; nf < 4; nf++)
                #pragma unroll
                for (int e = 0; e < 4; e++) oacc[nf][e] = 0.f;

            const uint32_t vA = sVt +
                (uint32_t)((hr + (lane & 15)) * TP + (lane >> 4) * 16 + W8) * 2u;
            #pragma unroll
            for (int ks = 0; ks < 4; ks++) {
                #pragma unroll
                for (int ng = 0; ng < 2; ng++) {
                    uint32_t vh[4];
                    LDSM4(vh, vA + ng * 16 * TP * 2 + ks * 64);
                    MMAF16(oacc[2 * ng],     pa[ks], vh[0], vh[2]);
                    MMAF16(oacc[2 * ng + 1], pa[ks], vh[1], vh[3]);
                }
            }

            // Store to sATT (reuses sX region; X dead after phase 2)
            {
                int r = lane >> 2, cb = (lane & 3) * 2;
                int col = wq * 32 + W8 + r;
                __half* ATT = (__half*)(smem + SX_B);
                #pragma unroll
                for (int nf = 0; nf < 4; nf++) {
                    int d = hr + nf * 8 + cb;
                    ATT[d * TP + col]            = __float2half_rn(oacc[nf][0]);
                    ATT[(d + 1) * TP + col]      = __float2half_rn(oacc[nf][1]);
                    ATT[d * TP + col + 16]       = __float2half_rn(oacc[nf][2]);
                    ATT[(d + 1) * TP + col + 16] = __float2half_rn(oacc[nf][3]);
                }
            }
        }
    }
    CP_WAIT0();
    __syncthreads();   // sATT complete; Wproj landed

    // --- Phase 4: proj GEMM from sATT + Wproj (slot1), warp tile 32x32 ---
    {
        const uint32_t aaddr = sb + SW1_B + aoff;
        float acc[2][4][4];
        #pragma unroll
        for (int mi = 0; mi < 2; mi++)
            #pragma unroll
            for (int nf = 0; nf < 4; nf++)
                #pragma unroll
                for (int e = 0; e < 4; e++) acc[mi][nf][e] = 0.f;

        #pragma unroll
        for (int ks = 0; ks < 8; ks++) {
            uint32_t a0[4], a1[4];
            LDSM4(a0, aaddr + ks * 32);
            LDSM4(a1, aaddr + 16 * TP * 2 + ks * 32);
            #pragma unroll
            for (int g = 0; g < 2; g++) {
                uint32_t bg[4];
                LDSM4T(bg, baddr + ks * 16 * TP * 2 + g * 32);
                MMAF16(acc[0][2 * g],     a0, bg[0], bg[1]);
                MMAF16(acc[0][2 * g + 1], a0, bg[2], bg[3]);
                MMAF16(acc[1][2 * g],     a1, bg[0], bg[1]);
                MMAF16(acc[1][2 * g + 1], a1, bg[2], bg[3]);
            }
        }

        // Epilogue: fp32 direct to gmem
        #pragma unroll
        for (int mi = 0; mi < 2; mi++) {
            int r = wm * 32 + mi * 16 + (lane >> 2);
            float bv0 = proj_b[r], bv1 = proj_b[r + 8];
            float* O0 = out + ((size_t)b * CCH + r) * HWSZ + sp0;
            #pragma unroll
            for (int nf = 0; nf < 4; nf++) {
                int col = wn * 32 + nf * 8 + (lane & 3) * 2;
                int gpos = (col >> 4) * WW + (col & 15);
                *(float2*)(O0 + gpos) =
                    make_float2(acc[mi][nf][0] + bv0, acc[mi][nf][1] + bv0);
                *(float2*)(O0 + (size_t)8 * HWSZ + gpos) =
                    make_float2(acc[mi][nf][2] + bv1, acc[mi][nf][3] + bv1);
            }
        }
    }
}

// ---------------------------------------------------------------------------
// Launch
// ---------------------------------------------------------------------------
extern "C" void kernel_launch(void* const* d_in, const int* in_sizes, int n_in,
                              void* d_out, int out_size)
{
    const float* x      = (const float*)d_in[0];
    const float* norm_w = (const float*)d_in[1];
    const float* norm_b = (const float*)d_in[2];
    const float* qkv_w  = (const float*)d_in[3];
    const float* qkv_b  = (const float*)d_in[4];
    const float* proj_w = (const float*)d_in[5];
    const float* proj_b = (const float*)d_in[6];
    float* out = (float*)d_out;

    float *na, *nb;
    __half *wf;
    cudaGetSymbolAddress((void**)&na, g_na);
    cudaGetSymbolAddress((void**)&nb, g_nb);
    cudaGetSymbolAddress((void**)&wf, g_wf);

    cudaFuncSetAttribute(fused_kernel,
                         cudaFuncAttributeMaxDynamicSharedMemorySize, FUSED_SMEM);

    // 0) Weight convert (tiny)
    wconv_kernel<<<(4 * CCH * CCH + 255) / 256, 256>>>(qkv_w, proj_w, wf);

    // 1) LayerNorm stats
    ln_stats_kernel<<<BATCH * CCH, 256>>>(x, norm_w, norm_b, na, nb);

    // 2) Fused LN-affine + QKV + attention + proj (512 threads)
    fused_kernel<<<dim3(NWIN / 2, NWIN, BATCH), 512, FUSED_SMEM>>>(
        x, wf, qkv_b, proj_b, out, na, nb);
}